// round 14
// baseline (speedup 1.0000x reference)
#include <cuda_runtime.h>
#include <cuda_fp16.h>
#include <math.h>
#include <stdint.h>

#define NN 10000
#define NE 60000
#define DD 128
#define NLAYERS 15

#define ERT 3750   // edge row tiles (60000/16)
#define NRT 625    // node row tiles (10000/16)

// ---------------- device scratch (allocation-free) ----------------
__device__ float g_agg[NN * DD];    // per-node aggregated edge features
__device__ float g_cnt[NN];         // 1/max(count,1)
__device__ float g_X1[NN * 512];    // per-node [x@W1a + b1 | x@W1b] (fp32)

// weights pre-packed as B-fragments {bh0,bh1,bl0,bl1} (fp16 hi/lo):
// layout [layer][ktile][ntile][lane]
__device__ uint4 g_ew1a[NLAYERS * 8 * 32 * 32];   // W1 rows 0..127   (x[row] part)
__device__ uint4 g_ew1b[NLAYERS * 8 * 32 * 32];   // W1 rows 128..255 (x[col] part)
__device__ uint4 g_ew1c[NLAYERS * 8 * 32 * 32];   // W1 rows 256..383 (ea part)
__device__ uint4 g_ew2p[NLAYERS * 16 * 16 * 32];
__device__ uint4 g_nw1p[NLAYERS * 16 * 32 * 32];
__device__ uint4 g_nw2p[NLAYERS * 16 * 16 * 32];

// ---------------- helpers ----------------
__device__ __forceinline__ uint32_t pkh(float a, float b) {
    __half2 t = __floats2half2_rn(a, b);
    return *(uint32_t*)&t;
}
__device__ __forceinline__ uint32_t pkl(float a, float b) {
    __half ha = __float2half_rn(a), hb = __float2half_rn(b);
    return pkh(a - __half2float(ha), b - __half2float(hb));
}

// exact-GELU via Abramowitz-Stegun 7.1.26 erf (abs err <= 1.5e-7)
__device__ __forceinline__ float gelu_f(float t) {
    float x = fabsf(t) * 0.70710678118654752f;
    float k = __fdividef(1.f, fmaf(0.3275911f, x, 1.f));
    float p = fmaf(1.061405429f, k, -1.453152027f);
    p = fmaf(p, k, 1.421413741f);
    p = fmaf(p, k, -0.284496736f);
    p = fmaf(p, k, 0.254829592f);
    p = p * k;
    float e = __expf(-x * x);
    float er = copysignf(fmaf(-p, e, 1.f), t);
    return 0.5f * t * (1.f + er);
}

#define MMA4(d, a, b0, b1) \
    asm volatile("mma.sync.aligned.m16n8k16.row.col.f32.f16.f16.f32 " \
                 "{%0,%1,%2,%3},{%4,%5,%6,%7},{%8,%9},{%0,%1,%2,%3};" \
                 : "+f"((d).x), "+f"((d).y), "+f"((d).z), "+f"((d).w) \
                 : "r"((a)[0]), "r"((a)[1]), "r"((a)[2]), "r"((a)[3]), \
                   "r"(b0), "r"(b1))

#define REDV2(ptr, v0, v1) \
    asm volatile("red.global.add.v2.f32 [%0], {%1, %2};" \
                 :: "l"(ptr), "f"(v0), "f"(v1) : "memory")

// async B slab prefetch into 4-deep ring slot (kt & 3); always commits a group
template <int SLAB, int NTH>
__device__ __forceinline__ void pref_slab(uint4* sB, const uint4* Wp, int kt, int KT, int tid) {
    if (kt < KT) {
        const uint4* src = Wp + (size_t)kt * SLAB + tid;
        uint32_t dst = (uint32_t)__cvta_generic_to_shared(sB + (kt & 3) * SLAB + tid);
#pragma unroll
        for (int i = 0; i < SLAB / NTH; i++)
            asm volatile("cp.async.cg.shared.global [%0], [%1], 16;"
                         :: "r"(dst + i * NTH * 16), "l"(src + i * NTH));
    }
    asm volatile("cp.async.commit_group;" ::: "memory");
}
#define CPWAIT2() asm volatile("cp.async.wait_group 2;" ::: "memory")
#define CPWAIT0() asm volatile("cp.async.wait_group 0;" ::: "memory")

// ---------------- aux kernels ----------------
__global__ void copy_kernel(const float* __restrict__ src, float* __restrict__ dst, int n) {
    int i = blockIdx.x * blockDim.x + threadIdx.x;
    if (i < n) dst[i] = src[i];
}
__global__ void zero_cnt_kernel() {
    int i = blockIdx.x * blockDim.x + threadIdx.x;
    if (i < NN) g_cnt[i] = 0.f;
}
__global__ void count_kernel(const int* __restrict__ col) {
    int e = blockIdx.x * blockDim.x + threadIdx.x;
    if (e < NE) atomicAdd(&g_cnt[col[e]], 1.f);
}
__global__ void invcnt_kernel() {
    int i = blockIdx.x * blockDim.x + threadIdx.x;
    if (i < NN) g_cnt[i] = 1.f / fmaxf(g_cnt[i], 1.f);
}
__global__ void zero_agg_kernel() {
    int i = blockIdx.x * blockDim.x + threadIdx.x;
    if (i < NN * DD) g_agg[i] = 0.f;
}

// Pre-pack fp32 W[L][K][N] rows [k0, k0+16*KT) into per-lane B fragments.
__global__ void pack_w(const float* __restrict__ W, uint4* __restrict__ out,
                       int k0, int KT, int NT, int K, int N, int total) {
    int idx = blockIdx.x * blockDim.x + threadIdx.x;
    if (idx >= total) return;
    int lane = idx & 31;
    int t = idx >> 5;
    int nt = t % NT; t /= NT;
    int kt = t % KT;
    int l = t / KT;
    int g = lane >> 2, tg = lane & 3;
    const float* Wl = W + (size_t)l * K * N;
    int n = nt * 8 + g;
    int ka = k0 + kt * 16 + tg * 2;
    float v00 = Wl[(size_t)ka * N + n];
    float v01 = Wl[(size_t)(ka + 1) * N + n];
    float v10 = Wl[(size_t)(ka + 8) * N + n];
    float v11 = Wl[(size_t)(ka + 9) * N + n];
    uint4 o;
    o.x = pkh(v00, v01);
    o.y = pkh(v10, v11);
    o.z = pkl(v00, v01);
    o.w = pkl(v10, v11);
    out[idx] = o;
}

// ---------------- layer-0 node precompute: X1 = [x@W1a + b1 | x@W1b] ----------------
// blockIdx.y = 0: W1a half (adds bias), 1: W1b half. K=128 (8 ktiles), N=256.
// (layers 1..L-1 get X1 from node_fused phase 3)
__global__ void __launch_bounds__(128, 2)
pre_x1(const uint4* __restrict__ Wa, const uint4* __restrict__ Wb,
       const float* __restrict__ b1v, const float* __restrict__ xbuf) {
    constexpr int KT = 8, NT = 32, SLAB = NT * 32;
    extern __shared__ uint4 sB[];

    const int tid = threadIdx.x, lane = tid & 31, warp = tid >> 5;
    const int g = lane >> 2, tg = lane & 3;
    const int half = blockIdx.y;
    const uint4* Wp = half ? Wb : Wa;
    const int rt = blockIdx.x * 4 + warp;
    const int r0 = rt * 16 + g, r1 = r0 + 8;
    const int r0c = min(r0, NN - 1), r1c = min(r1, NN - 1);
    const bool ok0 = r0 < NN, ok1 = r1 < NN;

    const float* p0 = xbuf + (size_t)r0c * DD;
    const float* p1 = xbuf + (size_t)r1c * DD;

    float4 acc[NT];
#pragma unroll
    for (int i = 0; i < NT; i++) acc[i] = make_float4(0.f, 0.f, 0.f, 0.f);

    pref_slab<SLAB, 128>(sB, Wp, 0, KT, tid);
    pref_slab<SLAB, 128>(sB, Wp, 1, KT, tid);
    pref_slab<SLAB, 128>(sB, Wp, 2, KT, tid);

    for (int kt = 0; kt < KT; kt++) {
        CPWAIT2();
        __syncthreads();
        int ko = kt * 16 + tg * 2;
        float2 a0 = *(const float2*)(p0 + ko);
        float2 a2 = *(const float2*)(p0 + ko + 8);
        float2 b0 = *(const float2*)(p1 + ko);
        float2 b2 = *(const float2*)(p1 + ko + 8);
        uint32_t ah[4];
        ah[0] = pkh(a0.x, a0.y); ah[1] = pkh(b0.x, b0.y);
        ah[2] = pkh(a2.x, a2.y); ah[3] = pkh(b2.x, b2.y);
        const uint4* Bs = sB + (kt & 3) * SLAB + lane;
#pragma unroll
        for (int nt = 0; nt < NT; nt++) {
            uint4 b = Bs[nt * 32];
            MMA4(acc[nt], ah, b.x, b.y);
            MMA4(acc[nt], ah, b.z, b.w);
        }
        pref_slab<SLAB, 128>(sB, Wp, kt + 3, KT, tid);
    }

    const int ofs = half * 256;
#pragma unroll
    for (int nt = 0; nt < NT; nt++) {
        int c = nt * 8 + tg * 2;
        float bx = half ? 0.f : b1v[c];
        float by = half ? 0.f : b1v[c + 1];
        if (ok0) *(float2*)&g_X1[(size_t)r0 * 512 + ofs + c] =
            make_float2(acc[nt].x + bx, acc[nt].y + by);
        if (ok1) *(float2*)&g_X1[(size_t)r1 * 512 + ofs + c] =
            make_float2(acc[nt].z + bx, acc[nt].w + by);
    }
}

// ---------------- fused edge MLP kernel ----------------
// GEMM1 = ea@W1c (K=128) + gathered X1[row], X1[col] adds (bias pre-folded);
// LN1 + GELU -> register fp16 fragments; GEMM2 K=256 N=128; LN2 + residual(ea)
// + red.v2 scatter into g_agg[col]. 4 warps/CTA, min 2 CTAs/SM.
__global__ void __launch_bounds__(128, 2)
edge_fused(const uint4* __restrict__ W1, const uint4* __restrict__ W2,
           const float* __restrict__ g1v, const float* __restrict__ bt1v,
           const float* __restrict__ b2v, const float* __restrict__ g2v, const float* __restrict__ bt2v,
           float* __restrict__ eabuf,
           const int* __restrict__ rowi, const int* __restrict__ coli) {
    constexpr int KT1 = 8, NT1 = 32, SLAB1 = NT1 * 32;
    constexpr int KT2 = 16, NT2 = 16, SLAB2 = NT2 * 32;
    extern __shared__ uint4 sB[];

    const int tid = threadIdx.x, lane = tid & 31, warp = tid >> 5;
    const int g = lane >> 2, tg = lane & 3;
    const int rt = blockIdx.x * 4 + warp;
    const int r0 = rt * 16 + g, r1 = r0 + 8;
    const int r0c = min(r0, NE - 1), r1c = min(r1, NE - 1);
    const bool ok0 = r0 < NE, ok1 = r1 < NE;

    const int n0r = rowi[r0c], n0c = coli[r0c];
    const int n1r = rowi[r1c], n1c = coli[r1c];
    const float* p02 = eabuf + (size_t)r0c * DD;
    const float* p12 = eabuf + (size_t)r1c * DD;

    // ---- phase 1: GEMM1 (ea @ W1c) ----
    float4 acc[NT1];
#pragma unroll
    for (int i = 0; i < NT1; i++) acc[i] = make_float4(0.f, 0.f, 0.f, 0.f);

    pref_slab<SLAB1, 128>(sB, W1, 0, KT1, tid);
    pref_slab<SLAB1, 128>(sB, W1, 1, KT1, tid);
    pref_slab<SLAB1, 128>(sB, W1, 2, KT1, tid);

    for (int kt = 0; kt < KT1; kt++) {
        CPWAIT2();
        __syncthreads();
        int ko = kt * 16 + tg * 2;
        float2 a0 = *(const float2*)(p02 + ko);
        float2 a2 = *(const float2*)(p02 + ko + 8);
        float2 b0 = *(const float2*)(p12 + ko);
        float2 b2 = *(const float2*)(p12 + ko + 8);
        uint32_t ah[4];
        ah[0] = pkh(a0.x, a0.y); ah[1] = pkh(b0.x, b0.y);
        ah[2] = pkh(a2.x, a2.y); ah[3] = pkh(b2.x, b2.y);
        const uint4* Bs = sB + (kt & 3) * SLAB1 + lane;
#pragma unroll
        for (int nt = 0; nt < NT1; nt++) {
            uint4 b = Bs[nt * 32];
            MMA4(acc[nt], ah, b.x, b.y);
            MMA4(acc[nt], ah, b.z, b.w);
        }
        pref_slab<SLAB1, 128>(sB, W1, kt + 3, KT1, tid);
    }

    // ---- gather-add X1 rows + LN1 stats ----
    const float* xa0 = g_X1 + (size_t)n0r * 512;
    const float* xb0 = g_X1 + (size_t)n0c * 512 + 256;
    const float* xa1 = g_X1 + (size_t)n1r * 512;
    const float* xb1 = g_X1 + (size_t)n1c * 512 + 256;
    float s0 = 0.f, q0s = 0.f, s1 = 0.f, q1s = 0.f;
#pragma unroll
    for (int nt = 0; nt < NT1; nt++) {
        int c = nt * 8 + tg * 2;
        float2 va = *(const float2*)(xa0 + c);
        float2 vb = *(const float2*)(xb0 + c);
        float2 vc = *(const float2*)(xa1 + c);
        float2 vd = *(const float2*)(xb1 + c);
        acc[nt].x += va.x + vb.x; acc[nt].y += va.y + vb.y;
        acc[nt].z += vc.x + vd.x; acc[nt].w += vc.y + vd.y;
        s0 += acc[nt].x + acc[nt].y;
        q0s += acc[nt].x * acc[nt].x + acc[nt].y * acc[nt].y;
        s1 += acc[nt].z + acc[nt].w;
        q1s += acc[nt].z * acc[nt].z + acc[nt].w * acc[nt].w;
    }
#pragma unroll
    for (int off = 1; off <= 2; off <<= 1) {
        s0 += __shfl_xor_sync(0xffffffffu, s0, off);
        q0s += __shfl_xor_sync(0xffffffffu, q0s, off);
        s1 += __shfl_xor_sync(0xffffffffu, s1, off);
        q1s += __shfl_xor_sync(0xffffffffu, q1s, off);
    }
    float m0 = s0 * (1.f / 256.f), v0 = q0s * (1.f / 256.f) - m0 * m0, rs0 = rsqrtf(v0 + 1e-5f);
    float m1 = s1 * (1.f / 256.f), v1 = q1s * (1.f / 256.f) - m1 * m1, rs1 = rsqrtf(v1 + 1e-5f);

    // ---- phase boundary: drain ring, start phase-2 prefetch, then GELU epilogue ----
    CPWAIT0();
    __syncthreads();
    pref_slab<SLAB2, 128>(sB, W2, 0, KT2, tid);
    pref_slab<SLAB2, 128>(sB, W2, 1, KT2, tid);
    pref_slab<SLAB2, 128>(sB, W2, 2, KT2, tid);

    uint4 hf[16];  // hidden rows as fp16 A-fragments for GEMM2
#pragma unroll
    for (int kt = 0; kt < 16; kt++) {
        int c = kt * 16 + tg * 2;
        float ga0 = g1v[c], ga1 = g1v[c + 1], be0 = bt1v[c], be1 = bt1v[c + 1];
        float ga2 = g1v[c + 8], ga3 = g1v[c + 9], be2 = bt1v[c + 8], be3 = bt1v[c + 9];
        float tv[8];
        tv[0] = (acc[2 * kt].x - m0) * rs0 * ga0 + be0;
        tv[1] = (acc[2 * kt].y - m0) * rs0 * ga1 + be1;
        tv[2] = (acc[2 * kt].z - m1) * rs1 * ga0 + be0;
        tv[3] = (acc[2 * kt].w - m1) * rs1 * ga1 + be1;
        tv[4] = (acc[2 * kt + 1].x - m0) * rs0 * ga2 + be2;
        tv[5] = (acc[2 * kt + 1].y - m0) * rs0 * ga3 + be3;
        tv[6] = (acc[2 * kt + 1].z - m1) * rs1 * ga2 + be2;
        tv[7] = (acc[2 * kt + 1].w - m1) * rs1 * ga3 + be3;
#pragma unroll
        for (int j = 0; j < 8; j++) tv[j] = gelu_f(tv[j]);
        hf[kt].x = pkh(tv[0], tv[1]); hf[kt].y = pkh(tv[2], tv[3]);
        hf[kt].z = pkh(tv[4], tv[5]); hf[kt].w = pkh(tv[6], tv[7]);
    }

    // ---- phase 2: GEMM2 (A from registers) ----
    float4 acc2[NT2];
#pragma unroll
    for (int i = 0; i < NT2; i++) acc2[i] = make_float4(0.f, 0.f, 0.f, 0.f);

    for (int kt = 0; kt < KT2; kt++) {
        CPWAIT2();
        __syncthreads();
        uint32_t ah[4] = {hf[kt].x, hf[kt].y, hf[kt].z, hf[kt].w};
        const uint4* Bs = sB + (kt & 3) * SLAB2 + lane;
#pragma unroll
        for (int nt = 0; nt < NT2; nt++) {
            uint4 b = Bs[nt * 32];
            MMA4(acc2[nt], ah, b.x, b.y);
            MMA4(acc2[nt], ah, b.z, b.w);
        }
        pref_slab<SLAB2, 128>(sB, W2, kt + 3, KT2, tid);
    }

    // ---- LN2 + residual(ea) + agg scatter (red.v2) ----
    s0 = 0.f; q0s = 0.f; s1 = 0.f; q1s = 0.f;
#pragma unroll
    for (int nt = 0; nt < NT2; nt++) {
        int c = nt * 8 + tg * 2;
        float bx = b2v[c], by = b2v[c + 1];
        acc2[nt].x += bx; acc2[nt].y += by;
        acc2[nt].z += bx; acc2[nt].w += by;
        s0 += acc2[nt].x + acc2[nt].y;
        q0s += acc2[nt].x * acc2[nt].x + acc2[nt].y * acc2[nt].y;
        s1 += acc2[nt].z + acc2[nt].w;
        q1s += acc2[nt].z * acc2[nt].z + acc2[nt].w * acc2[nt].w;
    }
#pragma unroll
    for (int off = 1; off <= 2; off <<= 1) {
        s0 += __shfl_xor_sync(0xffffffffu, s0, off);
        q0s += __shfl_xor_sync(0xffffffffu, q0s, off);
        s1 += __shfl_xor_sync(0xffffffffu, s1, off);
        q1s += __shfl_xor_sync(0xffffffffu, q1s, off);
    }
    m0 = s0 * (1.f / 128.f); v0 = q0s * (1.f / 128.f) - m0 * m0; rs0 = rsqrtf(v0 + 1e-5f);
    m1 = s1 * (1.f / 128.f); v1 = q1s * (1.f / 128.f) - m1 * m1; rs1 = rsqrtf(v1 + 1e-5f);

#pragma unroll
    for (int nt = 0; nt < NT2; nt++) {
        int c = nt * 8 + tg * 2;
        float ga0 = g2v[c], ga1 = g2v[c + 1], be0 = bt2v[c], be1 = bt2v[c + 1];
        if (ok0) {
            float t0 = (acc2[nt].x - m0) * rs0 * ga0 + be0;
            float t1 = (acc2[nt].y - m0) * rs0 * ga1 + be1;
            float2 e = *(float2*)&eabuf[(size_t)r0 * DD + c];
            e.x += t0; e.y += t1;
            *(float2*)&eabuf[(size_t)r0 * DD + c] = e;
            REDV2(&g_agg[(size_t)n0c * DD + c], e.x, e.y);
        }
        if (ok1) {
            float t0 = (acc2[nt].z - m1) * rs1 * ga0 + be0;
            float t1 = (acc2[nt].w - m1) * rs1 * ga1 + be1;
            float2 e = *(float2*)&eabuf[(size_t)r1 * DD + c];
            e.x += t0; e.y += t1;
            *(float2*)&eabuf[(size_t)r1 * DD + c] = e;
            REDV2(&g_agg[(size_t)n1c * DD + c], e.x, e.y);
        }
    }
}

// ---------------- fused node MLP kernel (+ X1 precompute for next layer) ----------------
// A1=[x | agg*invcnt] K=256 N=256 (re-zeroes agg for next layer);
// GEMM2 K=256 N=128; x += LN2. Phase 3: new-x fragments (held in registers)
// -> X1 = [x@W1a' + b1' | x@W1b'] for the NEXT layer. 4 warps/CTA, 2 CTAs/SM.
__global__ void __launch_bounds__(128, 2)
node_fused(const uint4* __restrict__ W1, const uint4* __restrict__ W2,
           const float* __restrict__ b1v, const float* __restrict__ g1v, const float* __restrict__ bt1v,
           const float* __restrict__ b2v, const float* __restrict__ g2v, const float* __restrict__ bt2v,
           float* __restrict__ xbuf,
           const uint4* __restrict__ W1an, const uint4* __restrict__ W1bn,
           const float* __restrict__ b1n, int do_x1) {
    constexpr int KT1 = 16, NT1 = 32, SLAB1 = NT1 * 32;
    constexpr int KT2 = 16, NT2 = 16, SLAB2 = NT2 * 32;
    extern __shared__ uint4 sB[];

    const int tid = threadIdx.x, lane = tid & 31, warp = tid >> 5;
    const int g = lane >> 2, tg = lane & 3;
    const int rt = blockIdx.x * 4 + warp;
    const int r0 = rt * 16 + g, r1 = r0 + 8;
    const int r0c = min(r0, NN - 1), r1c = min(r1, NN - 1);
    const bool ok0 = r0 < NN, ok1 = r1 < NN;

    const float* p00 = xbuf + (size_t)r0c * DD;
    float* p01 = g_agg + (size_t)r0c * DD;
    const float* p10 = xbuf + (size_t)r1c * DD;
    float* p11 = g_agg + (size_t)r1c * DD;
    const float ic0 = g_cnt[r0c], ic1 = g_cnt[r1c];

    auto loadA = [&](int kt, float2& a0, float2& a2, float2& b0, float2& b2) {
        int seg = kt >> 3, ko = (kt & 7) * 16 + tg * 2;
        const float* q0 = seg == 0 ? p00 : p01;
        const float* q1 = seg == 0 ? p10 : p11;
        a0 = *(const float2*)(q0 + ko); a2 = *(const float2*)(q0 + ko + 8);
        b0 = *(const float2*)(q1 + ko); b2 = *(const float2*)(q1 + ko + 8);
        if (seg == 1) {
            // each agg element read exactly once per layer: zero it for the next
            // layer's scatter. Guarded so clamped (out-of-range) warps never write.
            float2 z = make_float2(0.f, 0.f);
            if (ok0) { *(float2*)(p01 + ko) = z; *(float2*)(p01 + ko + 8) = z; }
            if (ok1) { *(float2*)(p11 + ko) = z; *(float2*)(p11 + ko + 8) = z; }
        }
    };

    // ---- phase 1: GEMM1 ----
    float4 acc[NT1];
#pragma unroll
    for (int i = 0; i < NT1; i++) acc[i] = make_float4(0.f, 0.f, 0.f, 0.f);

    pref_slab<SLAB1, 128>(sB, W1, 0, KT1, tid);
    pref_slab<SLAB1, 128>(sB, W1, 1, KT1, tid);
    pref_slab<SLAB1, 128>(sB, W1, 2, KT1, tid);
    float2 ca0, ca2, cb0, cb2;
    loadA(0, ca0, ca2, cb0, cb2);

    for (int kt = 0; kt < KT1; kt++) {
        CPWAIT2();
        __syncthreads();
        float2 na0 = ca0, na2 = ca2, nb0 = cb0, nb2 = cb2;
        if (kt + 1 < KT1) loadA(kt + 1, na0, na2, nb0, nb2);
        float s0f = 1.f, s1f = 1.f;
        if ((kt >> 3) == 1) { s0f = ic0; s1f = ic1; }
        uint32_t ah[4];
        ah[0] = pkh(ca0.x * s0f, ca0.y * s0f);
        ah[1] = pkh(cb0.x * s1f, cb0.y * s1f);
        ah[2] = pkh(ca2.x * s0f, ca2.y * s0f);
        ah[3] = pkh(cb2.x * s1f, cb2.y * s1f);
        const uint4* Bs = sB + (kt & 3) * SLAB1 + lane;
#pragma unroll
        for (int nt = 0; nt < NT1; nt++) {
            uint4 b = Bs[nt * 32];
            MMA4(acc[nt], ah, b.x, b.y);
            MMA4(acc[nt], ah, b.z, b.w);
        }
        pref_slab<SLAB1, 128>(sB, W1, kt + 3, KT1, tid);
        ca0 = na0; ca2 = na2; cb0 = nb0; cb2 = nb2;
    }

    // ---- LN1 stats ----
    float s0 = 0.f, q0s = 0.f, s1 = 0.f, q1s = 0.f;
#pragma unroll
    for (int nt = 0; nt < NT1; nt++) {
        int c = nt * 8 + tg * 2;
        float bx = b1v[c], by = b1v[c + 1];
        acc[nt].x += bx; acc[nt].y += by;
        acc[nt].z += bx; acc[nt].w += by;
        s0 += acc[nt].x + acc[nt].y;
        q0s += acc[nt].x * acc[nt].x + acc[nt].y * acc[nt].y;
        s1 += acc[nt].z + acc[nt].w;
        q1s += acc[nt].z * acc[nt].z + acc[nt].w * acc[nt].w;
    }
#pragma unroll
    for (int off = 1; off <= 2; off <<= 1) {
        s0 += __shfl_xor_sync(0xffffffffu, s0, off);
        q0s += __shfl_xor_sync(0xffffffffu, q0s, off);
        s1 += __shfl_xor_sync(0xffffffffu, s1, off);
        q1s += __shfl_xor_sync(0xffffffffu, q1s, off);
    }
    float m0 = s0 * (1.f / 256.f), v0 = q0s * (1.f / 256.f) - m0 * m0, rs0 = rsqrtf(v0 + 1e-5f);
    float m1 = s1 * (1.f / 256.f), v1 = q1s * (1.f / 256.f) - m1 * m1, rs1 = rsqrtf(v1 + 1e-5f);

    // ---- phase boundary ----
    CPWAIT0();
    __syncthreads();
    pref_slab<SLAB2, 128>(sB, W2, 0, KT2, tid);
    pref_slab<SLAB2, 128>(sB, W2, 1, KT2, tid);
    pref_slab<SLAB2, 128>(sB, W2, 2, KT2, tid);

    uint4 hf[16];
#pragma unroll
    for (int kt = 0; kt < 16; kt++) {
        int c = kt * 16 + tg * 2;
        float ga0 = g1v[c], ga1 = g1v[c + 1], be0 = bt1v[c], be1 = bt1v[c + 1];
        float ga2 = g1v[c + 8], ga3 = g1v[c + 9], be2 = bt1v[c + 8], be3 = bt1v[c + 9];
        float tv[8];
        tv[0] = (acc[2 * kt].x - m0) * rs0 * ga0 + be0;
        tv[1] = (acc[2 * kt].y - m0) * rs0 * ga1 + be1;
        tv[2] = (acc[2 * kt].z - m1) * rs1 * ga0 + be0;
        tv[3] = (acc[2 * kt].w - m1) * rs1 * ga1 + be1;
        tv[4] = (acc[2 * kt + 1].x - m0) * rs0 * ga2 + be2;
        tv[5] = (acc[2 * kt + 1].y - m0) * rs0 * ga3 + be3;
        tv[6] = (acc[2 * kt + 1].z - m1) * rs1 * ga2 + be2;
        tv[7] = (acc[2 * kt + 1].w - m1) * rs1 * ga3 + be3;
#pragma unroll
        for (int j = 0; j < 8; j++) tv[j] = gelu_f(tv[j]);
        hf[kt].x = pkh(tv[0], tv[1]); hf[kt].y = pkh(tv[2], tv[3]);
        hf[kt].z = pkh(tv[4], tv[5]); hf[kt].w = pkh(tv[6], tv[7]);
    }

    // ---- phase 2: GEMM2 ----
    float4 acc2[NT2];
#pragma unroll
    for (int i = 0; i < NT2; i++) acc2[i] = make_float4(0.f, 0.f, 0.f, 0.f);

    for (int kt = 0; kt < KT2; kt++) {
        CPWAIT2();
        __syncthreads();
        uint32_t ah[4] = {hf[kt].x, hf[kt].y, hf[kt].z, hf[kt].w};
        const uint4* Bs = sB + (kt & 3) * SLAB2 + lane;
#pragma unroll
        for (int nt = 0; nt < NT2; nt++) {
            uint4 b = Bs[nt * 32];
            MMA4(acc2[nt], ah, b.x, b.y);
            MMA4(acc2[nt], ah, b.z, b.w);
        }
        pref_slab<SLAB2, 128>(sB, W2, kt + 3, KT2, tid);
    }

    // early phase-3 prefetch (slots 0..2 are no longer read; lagging warps only
    // touch slot 3 in their final kt=15 mma)
    if (do_x1) {
        pref_slab<SLAB1, 128>(sB, W1an, 0, 8, tid);
        pref_slab<SLAB1, 128>(sB, W1an, 1, 8, tid);
        pref_slab<SLAB1, 128>(sB, W1an, 2, 8, tid);
    }

    // ---- LN2 + residual(x) + pack new-x fragments ----
    s0 = 0.f; q0s = 0.f; s1 = 0.f; q1s = 0.f;
#pragma unroll
    for (int nt = 0; nt < NT2; nt++) {
        int c = nt * 8 + tg * 2;
        float bx = b2v[c], by = b2v[c + 1];
        acc2[nt].x += bx; acc2[nt].y += by;
        acc2[nt].z += bx; acc2[nt].w += by;
        s0 += acc2[nt].x + acc2[nt].y;
        q0s += acc2[nt].x * acc2[nt].x + acc2[nt].y * acc2[nt].y;
        s1 += acc2[nt].z + acc2[nt].w;
        q1s += acc2[nt].z * acc2[nt].z + acc2[nt].w * acc2[nt].w;
    }
#pragma unroll
    for (int off = 1; off <= 2; off <<= 1) {
        s0 += __shfl_xor_sync(0xffffffffu, s0, off);
        q0s += __shfl_xor_sync(0xffffffffu, q0s, off);
        s1 += __shfl_xor_sync(0xffffffffu, s1, off);
        q1s += __shfl_xor_sync(0xffffffffu, q1s, off);
    }
    m0 = s0 * (1.f / 128.f); v0 = q0s * (1.f / 128.f) - m0 * m0; rs0 = rsqrtf(v0 + 1e-5f);
    m1 = s1 * (1.f / 128.f); v1 = q1s * (1.f / 128.f) - m1 * m1; rs1 = rsqrtf(v1 + 1e-5f);

    uint4 x16[8];  // new-x rows as fp16 A-fragments (K=128 -> 8 ktiles)
#pragma unroll
    for (int nt = 0; nt < NT2; nt++) {
        int c = nt * 8 + tg * 2;
        float ga0 = g2v[c], ga1 = g2v[c + 1], be0 = bt2v[c], be1 = bt2v[c + 1];
        float t0 = (acc2[nt].x - m0) * rs0 * ga0 + be0;
        float t1 = (acc2[nt].y - m0) * rs0 * ga1 + be1;
        float2 e0 = *(float2*)&xbuf[(size_t)r0c * DD + c];
        e0.x += t0; e0.y += t1;
        if (ok0) *(float2*)&xbuf[(size_t)r0 * DD + c] = e0;
        float t2 = (acc2[nt].z - m1) * rs1 * ga0 + be0;
        float t3 = (acc2[nt].w - m1) * rs1 * ga1 + be1;
        float2 e1 = *(float2*)&xbuf[(size_t)r1c * DD + c];
        e1.x += t2; e1.y += t3;
        if (ok1) *(float2*)&xbuf[(size_t)r1 * DD + c] = e1;
        uint32_t ph0 = pkh(e0.x, e0.y), ph1 = pkh(e1.x, e1.y);
        if (nt & 1) { x16[nt >> 1].z = ph0; x16[nt >> 1].w = ph1; }
        else        { x16[nt >> 1].x = ph0; x16[nt >> 1].y = ph1; }
    }

    // ---- phase 3: X1 for next layer from register fragments ----
    if (do_x1) {
#pragma unroll
        for (int half = 0; half < 2; half++) {
            const uint4* Wp = half ? W1bn : W1an;
            if (half) {
                pref_slab<SLAB1, 128>(sB, W1bn, 0, 8, tid);
                pref_slab<SLAB1, 128>(sB, W1bn, 1, 8, tid);
                pref_slab<SLAB1, 128>(sB, W1bn, 2, 8, tid);
            }
            float4 acc3[NT1];
#pragma unroll
            for (int i = 0; i < NT1; i++) acc3[i] = make_float4(0.f, 0.f, 0.f, 0.f);
            for (int kt = 0; kt < 8; kt++) {
                CPWAIT2();
                __syncthreads();
                uint32_t ah[4] = {x16[kt].x, x16[kt].y, x16[kt].z, x16[kt].w};
                const uint4* Bs = sB + (kt & 3) * SLAB1 + lane;
#pragma unroll
                for (int nt = 0; nt < NT1; nt++) {
                    uint4 b = Bs[nt * 32];
                    MMA4(acc3[nt], ah, b.x, b.y);
                    MMA4(acc3[nt], ah, b.z, b.w);
                }
                pref_slab<SLAB1, 128>(sB, Wp, kt + 3, 8, tid);
            }
            const int ofs = half * 256;
#pragma unroll
            for (int nt = 0; nt < NT1; nt++) {
                int c = nt * 8 + tg * 2;
                float bx = half ? 0.f : b1n[c];
                float by = half ? 0.f : b1n[c + 1];
                if (ok0) *(float2*)&g_X1[(size_t)r0 * 512 + ofs + c] =
                    make_float2(acc3[nt].x + bx, acc3[nt].y + by);
                if (ok1) *(float2*)&g_X1[(size_t)r1 * 512 + ofs + c] =
                    make_float2(acc3[nt].z + bx, acc3[nt].w + by);
            }
        }
    }
}

// ---------------- host launcher ----------------
extern "C" void kernel_launch(void* const* d_in, const int* in_sizes, int n_in,
                              void* d_out, int out_size) {
    const float* x    = (const float*)d_in[0];
    const int*   ei   = (const int*)d_in[1];
    const float* ea   = (const float*)d_in[2];
    const float* ew1  = (const float*)d_in[3];
    const float* eb1  = (const float*)d_in[4];
    const float* eg1  = (const float*)d_in[5];
    const float* ebt1 = (const float*)d_in[6];
    const float* ew2  = (const float*)d_in[7];
    const float* eb2  = (const float*)d_in[8];
    const float* eg2  = (const float*)d_in[9];
    const float* ebt2 = (const float*)d_in[10];
    const float* nw1  = (const float*)d_in[11];
    const float* nb1  = (const float*)d_in[12];
    const float* ng1  = (const float*)d_in[13];
    const float* nbt1 = (const float*)d_in[14];
    const float* nw2  = (const float*)d_in[15];
    const float* nb2  = (const float*)d_in[16];
    const float* ng2  = (const float*)d_in[17];
    const float* nbt2 = (const float*)d_in[18];

    float* xo = (float*)d_out;
    float* eo = xo + (size_t)NN * DD;
    const int* rowi = ei;
    const int* coli = ei + NE;

    uint4 *ew1a, *ew1b, *ew1c, *ew2p, *nw1p, *nw2p;
    cudaGetSymbolAddress((void**)&ew1a, g_ew1a);
    cudaGetSymbolAddress((void**)&ew1b, g_ew1b);
    cudaGetSymbolAddress((void**)&ew1c, g_ew1c);
    cudaGetSymbolAddress((void**)&ew2p, g_ew2p);
    cudaGetSymbolAddress((void**)&nw1p, g_nw1p);
    cudaGetSymbolAddress((void**)&nw2p, g_nw2p);

    const int SMEM = 4 * 32 * 32 * 16;  // 65536 (max slab ring)
    cudaFuncSetAttribute(pre_x1, cudaFuncAttributeMaxDynamicSharedMemorySize, SMEM);
    cudaFuncSetAttribute(edge_fused, cudaFuncAttributeMaxDynamicSharedMemorySize, SMEM);
    cudaFuncSetAttribute(node_fused, cudaFuncAttributeMaxDynamicSharedMemorySize, SMEM);

    // pack weights into B-fragment layout
    {
        int ta = NLAYERS * 8 * 32 * 32;
        int t2 = NLAYERS * 16 * 16 * 32;
        int t3 = NLAYERS * 16 * 32 * 32;
        pack_w<<<(ta + 255) / 256, 256>>>(ew1, ew1a, 0, 8, 32, 384, 256, ta);
        pack_w<<<(ta + 255) / 256, 256>>>(ew1, ew1b, 128, 8, 32, 384, 256, ta);
        pack_w<<<(ta + 255) / 256, 256>>>(ew1, ew1c, 256, 8, 32, 384, 256, ta);
        pack_w<<<(t2 + 255) / 256, 256>>>(ew2, ew2p, 0, 16, 16, 256, 128, t2);
        pack_w<<<(t3 + 255) / 256, 256>>>(nw1, nw1p, 0, 16, 32, 256, 256, t3);
        pack_w<<<(t2 + 255) / 256, 256>>>(nw2, nw2p, 0, 16, 16, 256, 128, t2);
    }

    copy_kernel<<<(NN * DD + 255) / 256, 256>>>(x, xo, NN * DD);
    copy_kernel<<<(NE * DD + 255) / 256, 256>>>(ea, eo, NE * DD);
    zero_cnt_kernel<<<(NN + 255) / 256, 256>>>();
    count_kernel<<<(NE + 255) / 256, 256>>>(coli);
    invcnt_kernel<<<(NN + 255) / 256, 256>>>();
    zero_agg_kernel<<<(NN * DD + 255) / 256, 256>>>();  // once; node phase-1 re-zeroes per layer

    const int EG = (ERT + 3) / 4;  // 938
    const int NG = (NRT + 3) / 4;  // 157

    // X1 for layer 0 (layers 1.. come from node_fused phase 3)
    pre_x1<<<dim3(NG, 2), 128, SMEM>>>(ew1a, ew1b, eb1, xo);

    for (int l = 0; l < NLAYERS; l++) {
        edge_fused<<<EG, 128, SMEM>>>(
            ew1c + (size_t)l * 8 * 32 * 32, ew2p + (size_t)l * 16 * 16 * 32,
            eg1 + l * 256, ebt1 + l * 256,
            eb2 + l * 128, eg2 + l * 128, ebt2 + l * 128,
            eo, rowi, coli);
        int nl = (l + 1 < NLAYERS) ? (l + 1) : l;
        node_fused<<<NG, 128, SMEM>>>(
            nw1p + (size_t)l * 16 * 32 * 32, nw2p + (size_t)l * 16 * 16 * 32,
            nb1 + l * 256, ng1 + l * 256, nbt1 + l * 256,
            nb2 + l * 128, ng2 + l * 128, nbt2 + l * 128,
            xo,
            ew1a + (size_t)nl * 8 * 32 * 32, ew1b + (size_t)nl * 8 * 32 * 32,
            eb1 + nl * 256, (l + 1 < NLAYERS) ? 1 : 0);
    }
}

// round 15
// speedup vs baseline: 1.0201x; 1.0201x over previous
#include <cuda_runtime.h>
#include <cuda_fp16.h>
#include <math.h>
#include <stdint.h>

#define NN 10000
#define NE 60000
#define DD 128
#define NLAYERS 15

#define ERT 3750   // edge row tiles (60000/16)
#define NRT 625    // node row tiles (10000/16)

// ---------------- device scratch (allocation-free) ----------------
__device__ float g_agg[NN * DD];    // per-node aggregated edge features
__device__ float g_cnt[NN];         // 1/max(count,1)
__device__ float g_X1[NN * 512];    // per-node [x@W1a + b1 | x@W1b] (fp32)

// weights pre-packed as B-fragments {bh0,bh1,bl0,bl1} (fp16 hi/lo):
// layout [layer][ktile][ntile][lane]
__device__ uint4 g_ew1a[NLAYERS * 8 * 32 * 32];   // W1 rows 0..127   (x[row] part)
__device__ uint4 g_ew1b[NLAYERS * 8 * 32 * 32];   // W1 rows 128..255 (x[col] part)
__device__ uint4 g_ew1c[NLAYERS * 8 * 32 * 32];   // W1 rows 256..383 (ea part)
__device__ uint4 g_ew2p[NLAYERS * 16 * 16 * 32];
__device__ uint4 g_nw1p[NLAYERS * 16 * 32 * 32];
__device__ uint4 g_nw2p[NLAYERS * 16 * 16 * 32];

// ---------------- helpers ----------------
__device__ __forceinline__ uint32_t pkh(float a, float b) {
    __half2 t = __floats2half2_rn(a, b);
    return *(uint32_t*)&t;
}
__device__ __forceinline__ uint32_t pkl(float a, float b) {
    __half ha = __float2half_rn(a), hb = __float2half_rn(b);
    return pkh(a - __half2float(ha), b - __half2float(hb));
}

// exact-GELU via Abramowitz-Stegun 7.1.26 erf (abs err <= 1.5e-7)
__device__ __forceinline__ float gelu_f(float t) {
    float x = fabsf(t) * 0.70710678118654752f;
    float k = __fdividef(1.f, fmaf(0.3275911f, x, 1.f));
    float p = fmaf(1.061405429f, k, -1.453152027f);
    p = fmaf(p, k, 1.421413741f);
    p = fmaf(p, k, -0.284496736f);
    p = fmaf(p, k, 0.254829592f);
    p = p * k;
    float e = __expf(-x * x);
    float er = copysignf(fmaf(-p, e, 1.f), t);
    return 0.5f * t * (1.f + er);
}

#define MMA4(d, a, b0, b1) \
    asm volatile("mma.sync.aligned.m16n8k16.row.col.f32.f16.f16.f32 " \
                 "{%0,%1,%2,%3},{%4,%5,%6,%7},{%8,%9},{%0,%1,%2,%3};" \
                 : "+f"((d).x), "+f"((d).y), "+f"((d).z), "+f"((d).w) \
                 : "r"((a)[0]), "r"((a)[1]), "r"((a)[2]), "r"((a)[3]), \
                   "r"(b0), "r"(b1))

#define REDV2(ptr, v0, v1) \
    asm volatile("red.global.add.v2.f32 [%0], {%1, %2};" \
                 :: "l"(ptr), "f"(v0), "f"(v1) : "memory")

// async B slab prefetch into 4-deep ring slot (kt & 3); always commits a group
template <int SLAB, int NTH>
__device__ __forceinline__ void pref_slab(uint4* sB, const uint4* Wp, int kt, int KT, int tid) {
    if (kt < KT) {
        const uint4* src = Wp + (size_t)kt * SLAB + tid;
        uint32_t dst = (uint32_t)__cvta_generic_to_shared(sB + (kt & 3) * SLAB + tid);
#pragma unroll
        for (int i = 0; i < SLAB / NTH; i++)
            asm volatile("cp.async.cg.shared.global [%0], [%1], 16;"
                         :: "r"(dst + i * NTH * 16), "l"(src + i * NTH));
    }
    asm volatile("cp.async.commit_group;" ::: "memory");
}
#define CPWAIT2() asm volatile("cp.async.wait_group 2;" ::: "memory")
#define CPWAIT0() asm volatile("cp.async.wait_group 0;" ::: "memory")

// ---------------- aux kernels ----------------
__global__ void copy_kernel(const float* __restrict__ src, float* __restrict__ dst, int n) {
    int i = blockIdx.x * blockDim.x + threadIdx.x;
    if (i < n) dst[i] = src[i];
}
__global__ void zero_cnt_kernel() {
    int i = blockIdx.x * blockDim.x + threadIdx.x;
    if (i < NN) g_cnt[i] = 0.f;
}
__global__ void count_kernel(const int* __restrict__ col) {
    int e = blockIdx.x * blockDim.x + threadIdx.x;
    if (e < NE) atomicAdd(&g_cnt[col[e]], 1.f);
}
__global__ void invcnt_kernel() {
    int i = blockIdx.x * blockDim.x + threadIdx.x;
    if (i < NN) g_cnt[i] = 1.f / fmaxf(g_cnt[i], 1.f);
}
__global__ void zero_agg_kernel() {
    int i = blockIdx.x * blockDim.x + threadIdx.x;
    if (i < NN * DD) g_agg[i] = 0.f;
}

// Pre-pack fp32 W[L][K][N] rows [k0, k0+16*KT) into per-lane B fragments.
__global__ void pack_w(const float* __restrict__ W, uint4* __restrict__ out,
                       int k0, int KT, int NT, int K, int N, int total) {
    int idx = blockIdx.x * blockDim.x + threadIdx.x;
    if (idx >= total) return;
    int lane = idx & 31;
    int t = idx >> 5;
    int nt = t % NT; t /= NT;
    int kt = t % KT;
    int l = t / KT;
    int g = lane >> 2, tg = lane & 3;
    const float* Wl = W + (size_t)l * K * N;
    int n = nt * 8 + g;
    int ka = k0 + kt * 16 + tg * 2;
    float v00 = Wl[(size_t)ka * N + n];
    float v01 = Wl[(size_t)(ka + 1) * N + n];
    float v10 = Wl[(size_t)(ka + 8) * N + n];
    float v11 = Wl[(size_t)(ka + 9) * N + n];
    uint4 o;
    o.x = pkh(v00, v01);
    o.y = pkh(v10, v11);
    o.z = pkl(v00, v01);
    o.w = pkl(v10, v11);
    out[idx] = o;
}

// ---------------- per-layer node precompute: X1 = [x@W1a + b1 | x@W1b] ----------------
// blockIdx.y = 0: W1a half (adds bias), 1: W1b half. K=128 (8 ktiles), N=256.
__global__ void __launch_bounds__(128, 2)
pre_x1(const uint4* __restrict__ Wa, const uint4* __restrict__ Wb,
       const float* __restrict__ b1v, const float* __restrict__ xbuf) {
    constexpr int KT = 8, NT = 32, SLAB = NT * 32;
    extern __shared__ uint4 sB[];

    const int tid = threadIdx.x, lane = tid & 31, warp = tid >> 5;
    const int g = lane >> 2, tg = lane & 3;
    const int half = blockIdx.y;
    const uint4* Wp = half ? Wb : Wa;
    const int rt = blockIdx.x * 4 + warp;
    const int r0 = rt * 16 + g, r1 = r0 + 8;
    const int r0c = min(r0, NN - 1), r1c = min(r1, NN - 1);
    const bool ok0 = r0 < NN, ok1 = r1 < NN;

    const float* p0 = xbuf + (size_t)r0c * DD;
    const float* p1 = xbuf + (size_t)r1c * DD;

    float4 acc[NT];
#pragma unroll
    for (int i = 0; i < NT; i++) acc[i] = make_float4(0.f, 0.f, 0.f, 0.f);

    pref_slab<SLAB, 128>(sB, Wp, 0, KT, tid);
    pref_slab<SLAB, 128>(sB, Wp, 1, KT, tid);
    pref_slab<SLAB, 128>(sB, Wp, 2, KT, tid);

    for (int kt = 0; kt < KT; kt++) {
        CPWAIT2();
        __syncthreads();
        int ko = kt * 16 + tg * 2;
        float2 a0 = *(const float2*)(p0 + ko);
        float2 a2 = *(const float2*)(p0 + ko + 8);
        float2 b0 = *(const float2*)(p1 + ko);
        float2 b2 = *(const float2*)(p1 + ko + 8);
        uint32_t ah[4];
        ah[0] = pkh(a0.x, a0.y); ah[1] = pkh(b0.x, b0.y);
        ah[2] = pkh(a2.x, a2.y); ah[3] = pkh(b2.x, b2.y);
        const uint4* Bs = sB + (kt & 3) * SLAB + lane;
#pragma unroll
        for (int nt = 0; nt < NT; nt++) {
            uint4 b = Bs[nt * 32];
            MMA4(acc[nt], ah, b.x, b.y);
            MMA4(acc[nt], ah, b.z, b.w);
        }
        pref_slab<SLAB, 128>(sB, Wp, kt + 3, KT, tid);
    }

    const int ofs = half * 256;
#pragma unroll
    for (int nt = 0; nt < NT; nt++) {
        int c = nt * 8 + tg * 2;
        float bx = half ? 0.f : b1v[c];
        float by = half ? 0.f : b1v[c + 1];
        if (ok0) *(float2*)&g_X1[(size_t)r0 * 512 + ofs + c] =
            make_float2(acc[nt].x + bx, acc[nt].y + by);
        if (ok1) *(float2*)&g_X1[(size_t)r1 * 512 + ofs + c] =
            make_float2(acc[nt].z + bx, acc[nt].w + by);
    }
}

// ---------------- fused edge MLP kernel ----------------
// GEMM1 = ea@W1c (K=128) + gathered X1[row], X1[col] adds (bias pre-folded);
// LN1 + GELU -> register fp16 fragments; GEMM2 K=256 N=128; LN2 + residual(ea)
// + red.v2 scatter into g_agg[col]. 4 warps/CTA, min 2 CTAs/SM.
__global__ void __launch_bounds__(128, 2)
edge_fused(const uint4* __restrict__ W1, const uint4* __restrict__ W2,
           const float* __restrict__ g1v, const float* __restrict__ bt1v,
           const float* __restrict__ b2v, const float* __restrict__ g2v, const float* __restrict__ bt2v,
           float* __restrict__ eabuf,
           const int* __restrict__ rowi, const int* __restrict__ coli) {
    constexpr int KT1 = 8, NT1 = 32, SLAB1 = NT1 * 32;
    constexpr int KT2 = 16, NT2 = 16, SLAB2 = NT2 * 32;
    extern __shared__ uint4 sB[];

    const int tid = threadIdx.x, lane = tid & 31, warp = tid >> 5;
    const int g = lane >> 2, tg = lane & 3;
    const int rt = blockIdx.x * 4 + warp;
    const int r0 = rt * 16 + g, r1 = r0 + 8;
    const int r0c = min(r0, NE - 1), r1c = min(r1, NE - 1);
    const bool ok0 = r0 < NE, ok1 = r1 < NE;

    const int n0r = rowi[r0c], n0c = coli[r0c];
    const int n1r = rowi[r1c], n1c = coli[r1c];
    const float* p02 = eabuf + (size_t)r0c * DD;
    const float* p12 = eabuf + (size_t)r1c * DD;

    // ---- phase 1: GEMM1 (ea @ W1c) ----
    float4 acc[NT1];
#pragma unroll
    for (int i = 0; i < NT1; i++) acc[i] = make_float4(0.f, 0.f, 0.f, 0.f);

    pref_slab<SLAB1, 128>(sB, W1, 0, KT1, tid);
    pref_slab<SLAB1, 128>(sB, W1, 1, KT1, tid);
    pref_slab<SLAB1, 128>(sB, W1, 2, KT1, tid);

    for (int kt = 0; kt < KT1; kt++) {
        CPWAIT2();
        __syncthreads();
        int ko = kt * 16 + tg * 2;
        float2 a0 = *(const float2*)(p02 + ko);
        float2 a2 = *(const float2*)(p02 + ko + 8);
        float2 b0 = *(const float2*)(p12 + ko);
        float2 b2 = *(const float2*)(p12 + ko + 8);
        uint32_t ah[4];
        ah[0] = pkh(a0.x, a0.y); ah[1] = pkh(b0.x, b0.y);
        ah[2] = pkh(a2.x, a2.y); ah[3] = pkh(b2.x, b2.y);
        const uint4* Bs = sB + (kt & 3) * SLAB1 + lane;
#pragma unroll
        for (int nt = 0; nt < NT1; nt++) {
            uint4 b = Bs[nt * 32];
            MMA4(acc[nt], ah, b.x, b.y);
            MMA4(acc[nt], ah, b.z, b.w);
        }
        pref_slab<SLAB1, 128>(sB, W1, kt + 3, KT1, tid);
    }

    // ---- gather-add X1 rows + LN1 stats ----
    const float* xa0 = g_X1 + (size_t)n0r * 512;
    const float* xb0 = g_X1 + (size_t)n0c * 512 + 256;
    const float* xa1 = g_X1 + (size_t)n1r * 512;
    const float* xb1 = g_X1 + (size_t)n1c * 512 + 256;
    float s0 = 0.f, q0s = 0.f, s1 = 0.f, q1s = 0.f;
#pragma unroll
    for (int nt = 0; nt < NT1; nt++) {
        int c = nt * 8 + tg * 2;
        float2 va = *(const float2*)(xa0 + c);
        float2 vb = *(const float2*)(xb0 + c);
        float2 vc = *(const float2*)(xa1 + c);
        float2 vd = *(const float2*)(xb1 + c);
        acc[nt].x += va.x + vb.x; acc[nt].y += va.y + vb.y;
        acc[nt].z += vc.x + vd.x; acc[nt].w += vc.y + vd.y;
        s0 += acc[nt].x + acc[nt].y;
        q0s += acc[nt].x * acc[nt].x + acc[nt].y * acc[nt].y;
        s1 += acc[nt].z + acc[nt].w;
        q1s += acc[nt].z * acc[nt].z + acc[nt].w * acc[nt].w;
    }
#pragma unroll
    for (int off = 1; off <= 2; off <<= 1) {
        s0 += __shfl_xor_sync(0xffffffffu, s0, off);
        q0s += __shfl_xor_sync(0xffffffffu, q0s, off);
        s1 += __shfl_xor_sync(0xffffffffu, s1, off);
        q1s += __shfl_xor_sync(0xffffffffu, q1s, off);
    }
    float m0 = s0 * (1.f / 256.f), v0 = q0s * (1.f / 256.f) - m0 * m0, rs0 = rsqrtf(v0 + 1e-5f);
    float m1 = s1 * (1.f / 256.f), v1 = q1s * (1.f / 256.f) - m1 * m1, rs1 = rsqrtf(v1 + 1e-5f);

    // ---- phase boundary: drain ring, start phase-2 prefetch, then GELU epilogue ----
    CPWAIT0();
    __syncthreads();
    pref_slab<SLAB2, 128>(sB, W2, 0, KT2, tid);
    pref_slab<SLAB2, 128>(sB, W2, 1, KT2, tid);
    pref_slab<SLAB2, 128>(sB, W2, 2, KT2, tid);

    uint4 hf[16];  // hidden rows as fp16 A-fragments for GEMM2
#pragma unroll
    for (int kt = 0; kt < 16; kt++) {
        int c = kt * 16 + tg * 2;
        float ga0 = g1v[c], ga1 = g1v[c + 1], be0 = bt1v[c], be1 = bt1v[c + 1];
        float ga2 = g1v[c + 8], ga3 = g1v[c + 9], be2 = bt1v[c + 8], be3 = bt1v[c + 9];
        float tv[8];
        tv[0] = (acc[2 * kt].x - m0) * rs0 * ga0 + be0;
        tv[1] = (acc[2 * kt].y - m0) * rs0 * ga1 + be1;
        tv[2] = (acc[2 * kt].z - m1) * rs1 * ga0 + be0;
        tv[3] = (acc[2 * kt].w - m1) * rs1 * ga1 + be1;
        tv[4] = (acc[2 * kt + 1].x - m0) * rs0 * ga2 + be2;
        tv[5] = (acc[2 * kt + 1].y - m0) * rs0 * ga3 + be3;
        tv[6] = (acc[2 * kt + 1].z - m1) * rs1 * ga2 + be2;
        tv[7] = (acc[2 * kt + 1].w - m1) * rs1 * ga3 + be3;
#pragma unroll
        for (int j = 0; j < 8; j++) tv[j] = gelu_f(tv[j]);
        hf[kt].x = pkh(tv[0], tv[1]); hf[kt].y = pkh(tv[2], tv[3]);
        hf[kt].z = pkh(tv[4], tv[5]); hf[kt].w = pkh(tv[6], tv[7]);
    }

    // ---- phase 2: GEMM2 (A from registers) ----
    float4 acc2[NT2];
#pragma unroll
    for (int i = 0; i < NT2; i++) acc2[i] = make_float4(0.f, 0.f, 0.f, 0.f);

    for (int kt = 0; kt < KT2; kt++) {
        CPWAIT2();
        __syncthreads();
        uint32_t ah[4] = {hf[kt].x, hf[kt].y, hf[kt].z, hf[kt].w};
        const uint4* Bs = sB + (kt & 3) * SLAB2 + lane;
#pragma unroll
        for (int nt = 0; nt < NT2; nt++) {
            uint4 b = Bs[nt * 32];
            MMA4(acc2[nt], ah, b.x, b.y);
            MMA4(acc2[nt], ah, b.z, b.w);
        }
        pref_slab<SLAB2, 128>(sB, W2, kt + 3, KT2, tid);
    }

    // ---- LN2 + residual(ea) + agg scatter (red.v2) ----
    s0 = 0.f; q0s = 0.f; s1 = 0.f; q1s = 0.f;
#pragma unroll
    for (int nt = 0; nt < NT2; nt++) {
        int c = nt * 8 + tg * 2;
        float bx = b2v[c], by = b2v[c + 1];
        acc2[nt].x += bx; acc2[nt].y += by;
        acc2[nt].z += bx; acc2[nt].w += by;
        s0 += acc2[nt].x + acc2[nt].y;
        q0s += acc2[nt].x * acc2[nt].x + acc2[nt].y * acc2[nt].y;
        s1 += acc2[nt].z + acc2[nt].w;
        q1s += acc2[nt].z * acc2[nt].z + acc2[nt].w * acc2[nt].w;
    }
#pragma unroll
    for (int off = 1; off <= 2; off <<= 1) {
        s0 += __shfl_xor_sync(0xffffffffu, s0, off);
        q0s += __shfl_xor_sync(0xffffffffu, q0s, off);
        s1 += __shfl_xor_sync(0xffffffffu, s1, off);
        q1s += __shfl_xor_sync(0xffffffffu, q1s, off);
    }
    m0 = s0 * (1.f / 128.f); v0 = q0s * (1.f / 128.f) - m0 * m0; rs0 = rsqrtf(v0 + 1e-5f);
    m1 = s1 * (1.f / 128.f); v1 = q1s * (1.f / 128.f) - m1 * m1; rs1 = rsqrtf(v1 + 1e-5f);

#pragma unroll
    for (int nt = 0; nt < NT2; nt++) {
        int c = nt * 8 + tg * 2;
        float ga0 = g2v[c], ga1 = g2v[c + 1], be0 = bt2v[c], be1 = bt2v[c + 1];
        if (ok0) {
            float t0 = (acc2[nt].x - m0) * rs0 * ga0 + be0;
            float t1 = (acc2[nt].y - m0) * rs0 * ga1 + be1;
            float2 e = *(float2*)&eabuf[(size_t)r0 * DD + c];
            e.x += t0; e.y += t1;
            *(float2*)&eabuf[(size_t)r0 * DD + c] = e;
            REDV2(&g_agg[(size_t)n0c * DD + c], e.x, e.y);
        }
        if (ok1) {
            float t0 = (acc2[nt].z - m1) * rs1 * ga0 + be0;
            float t1 = (acc2[nt].w - m1) * rs1 * ga1 + be1;
            float2 e = *(float2*)&eabuf[(size_t)r1 * DD + c];
            e.x += t0; e.y += t1;
            *(float2*)&eabuf[(size_t)r1 * DD + c] = e;
            REDV2(&g_agg[(size_t)n1c * DD + c], e.x, e.y);
        }
    }
}

// ---------------- fused node MLP kernel ----------------
// A1=[x | agg*invcnt] K=256 N=256 (re-zeroes agg for next layer);
// GEMM2 K=256 N=128; out: x += LN2. 4 warps/CTA, min 2 CTAs/SM.
__global__ void __launch_bounds__(128, 2)
node_fused(const uint4* __restrict__ W1, const uint4* __restrict__ W2,
           const float* __restrict__ b1v, const float* __restrict__ g1v, const float* __restrict__ bt1v,
           const float* __restrict__ b2v, const float* __restrict__ g2v, const float* __restrict__ bt2v,
           float* __restrict__ xbuf) {
    constexpr int KT1 = 16, NT1 = 32, SLAB1 = NT1 * 32;
    constexpr int KT2 = 16, NT2 = 16, SLAB2 = NT2 * 32;
    extern __shared__ uint4 sB[];

    const int tid = threadIdx.x, lane = tid & 31, warp = tid >> 5;
    const int g = lane >> 2, tg = lane & 3;
    const int rt = blockIdx.x * 4 + warp;
    const int r0 = rt * 16 + g, r1 = r0 + 8;
    const int r0c = min(r0, NN - 1), r1c = min(r1, NN - 1);
    const bool ok0 = r0 < NN, ok1 = r1 < NN;

    const float* p00 = xbuf + (size_t)r0c * DD;
    float* p01 = g_agg + (size_t)r0c * DD;
    const float* p10 = xbuf + (size_t)r1c * DD;
    float* p11 = g_agg + (size_t)r1c * DD;
    const float ic0 = g_cnt[r0c], ic1 = g_cnt[r1c];

    auto loadA = [&](int kt, float2& a0, float2& a2, float2& b0, float2& b2) {
        int seg = kt >> 3, ko = (kt & 7) * 16 + tg * 2;
        const float* q0 = seg == 0 ? p00 : p01;
        const float* q1 = seg == 0 ? p10 : p11;
        a0 = *(const float2*)(q0 + ko); a2 = *(const float2*)(q0 + ko + 8);
        b0 = *(const float2*)(q1 + ko); b2 = *(const float2*)(q1 + ko + 8);
        if (seg == 1) {
            // each agg element read exactly once per layer: zero it for the next
            // layer's scatter. Guarded so clamped (out-of-range) warps never write.
            float2 z = make_float2(0.f, 0.f);
            if (ok0) { *(float2*)(p01 + ko) = z; *(float2*)(p01 + ko + 8) = z; }
            if (ok1) { *(float2*)(p11 + ko) = z; *(float2*)(p11 + ko + 8) = z; }
        }
    };

    // ---- phase 1: GEMM1 ----
    float4 acc[NT1];
#pragma unroll
    for (int i = 0; i < NT1; i++) acc[i] = make_float4(0.f, 0.f, 0.f, 0.f);

    pref_slab<SLAB1, 128>(sB, W1, 0, KT1, tid);
    pref_slab<SLAB1, 128>(sB, W1, 1, KT1, tid);
    pref_slab<SLAB1, 128>(sB, W1, 2, KT1, tid);
    float2 ca0, ca2, cb0, cb2;
    loadA(0, ca0, ca2, cb0, cb2);

    for (int kt = 0; kt < KT1; kt++) {
        CPWAIT2();
        __syncthreads();
        float2 na0 = ca0, na2 = ca2, nb0 = cb0, nb2 = cb2;
        if (kt + 1 < KT1) loadA(kt + 1, na0, na2, nb0, nb2);
        float s0f = 1.f, s1f = 1.f;
        if ((kt >> 3) == 1) { s0f = ic0; s1f = ic1; }
        uint32_t ah[4];
        ah[0] = pkh(ca0.x * s0f, ca0.y * s0f);
        ah[1] = pkh(cb0.x * s1f, cb0.y * s1f);
        ah[2] = pkh(ca2.x * s0f, ca2.y * s0f);
        ah[3] = pkh(cb2.x * s1f, cb2.y * s1f);
        const uint4* Bs = sB + (kt & 3) * SLAB1 + lane;
#pragma unroll
        for (int nt = 0; nt < NT1; nt++) {
            uint4 b = Bs[nt * 32];
            MMA4(acc[nt], ah, b.x, b.y);
            MMA4(acc[nt], ah, b.z, b.w);
        }
        pref_slab<SLAB1, 128>(sB, W1, kt + 3, KT1, tid);
        ca0 = na0; ca2 = na2; cb0 = nb0; cb2 = nb2;
    }

    // ---- LN1 stats ----
    float s0 = 0.f, q0s = 0.f, s1 = 0.f, q1s = 0.f;
#pragma unroll
    for (int nt = 0; nt < NT1; nt++) {
        int c = nt * 8 + tg * 2;
        float bx = b1v[c], by = b1v[c + 1];
        acc[nt].x += bx; acc[nt].y += by;
        acc[nt].z += bx; acc[nt].w += by;
        s0 += acc[nt].x + acc[nt].y;
        q0s += acc[nt].x * acc[nt].x + acc[nt].y * acc[nt].y;
        s1 += acc[nt].z + acc[nt].w;
        q1s += acc[nt].z * acc[nt].z + acc[nt].w * acc[nt].w;
    }
#pragma unroll
    for (int off = 1; off <= 2; off <<= 1) {
        s0 += __shfl_xor_sync(0xffffffffu, s0, off);
        q0s += __shfl_xor_sync(0xffffffffu, q0s, off);
        s1 += __shfl_xor_sync(0xffffffffu, s1, off);
        q1s += __shfl_xor_sync(0xffffffffu, q1s, off);
    }
    float m0 = s0 * (1.f / 256.f), v0 = q0s * (1.f / 256.f) - m0 * m0, rs0 = rsqrtf(v0 + 1e-5f);
    float m1 = s1 * (1.f / 256.f), v1 = q1s * (1.f / 256.f) - m1 * m1, rs1 = rsqrtf(v1 + 1e-5f);

    // ---- phase boundary ----
    CPWAIT0();
    __syncthreads();
    pref_slab<SLAB2, 128>(sB, W2, 0, KT2, tid);
    pref_slab<SLAB2, 128>(sB, W2, 1, KT2, tid);
    pref_slab<SLAB2, 128>(sB, W2, 2, KT2, tid);

    uint4 hf[16];
#pragma unroll
    for (int kt = 0; kt < 16; kt++) {
        int c = kt * 16 + tg * 2;
        float ga0 = g1v[c], ga1 = g1v[c + 1], be0 = bt1v[c], be1 = bt1v[c + 1];
        float ga2 = g1v[c + 8], ga3 = g1v[c + 9], be2 = bt1v[c + 8], be3 = bt1v[c + 9];
        float tv[8];
        tv[0] = (acc[2 * kt].x - m0) * rs0 * ga0 + be0;
        tv[1] = (acc[2 * kt].y - m0) * rs0 * ga1 + be1;
        tv[2] = (acc[2 * kt].z - m1) * rs1 * ga0 + be0;
        tv[3] = (acc[2 * kt].w - m1) * rs1 * ga1 + be1;
        tv[4] = (acc[2 * kt + 1].x - m0) * rs0 * ga2 + be2;
        tv[5] = (acc[2 * kt + 1].y - m0) * rs0 * ga3 + be3;
        tv[6] = (acc[2 * kt + 1].z - m1) * rs1 * ga2 + be2;
        tv[7] = (acc[2 * kt + 1].w - m1) * rs1 * ga3 + be3;
#pragma unroll
        for (int j = 0; j < 8; j++) tv[j] = gelu_f(tv[j]);
        hf[kt].x = pkh(tv[0], tv[1]); hf[kt].y = pkh(tv[2], tv[3]);
        hf[kt].z = pkh(tv[4], tv[5]); hf[kt].w = pkh(tv[6], tv[7]);
    }

    // ---- phase 2: GEMM2 ----
    float4 acc2[NT2];
#pragma unroll
    for (int i = 0; i < NT2; i++) acc2[i] = make_float4(0.f, 0.f, 0.f, 0.f);

    for (int kt = 0; kt < KT2; kt++) {
        CPWAIT2();
        __syncthreads();
        uint32_t ah[4] = {hf[kt].x, hf[kt].y, hf[kt].z, hf[kt].w};
        const uint4* Bs = sB + (kt & 3) * SLAB2 + lane;
#pragma unroll
        for (int nt = 0; nt < NT2; nt++) {
            uint4 b = Bs[nt * 32];
            MMA4(acc2[nt], ah, b.x, b.y);
            MMA4(acc2[nt], ah, b.z, b.w);
        }
        pref_slab<SLAB2, 128>(sB, W2, kt + 3, KT2, tid);
    }

    // ---- LN2 + residual(x) ----
    s0 = 0.f; q0s = 0.f; s1 = 0.f; q1s = 0.f;
#pragma unroll
    for (int nt = 0; nt < NT2; nt++) {
        int c = nt * 8 + tg * 2;
        float bx = b2v[c], by = b2v[c + 1];
        acc2[nt].x += bx; acc2[nt].y += by;
        acc2[nt].z += bx; acc2[nt].w += by;
        s0 += acc2[nt].x + acc2[nt].y;
        q0s += acc2[nt].x * acc2[nt].x + acc2[nt].y * acc2[nt].y;
        s1 += acc2[nt].z + acc2[nt].w;
        q1s += acc2[nt].z * acc2[nt].z + acc2[nt].w * acc2[nt].w;
    }
#pragma unroll
    for (int off = 1; off <= 2; off <<= 1) {
        s0 += __shfl_xor_sync(0xffffffffu, s0, off);
        q0s += __shfl_xor_sync(0xffffffffu, q0s, off);
        s1 += __shfl_xor_sync(0xffffffffu, s1, off);
        q1s += __shfl_xor_sync(0xffffffffu, q1s, off);
    }
    m0 = s0 * (1.f / 128.f); v0 = q0s * (1.f / 128.f) - m0 * m0; rs0 = rsqrtf(v0 + 1e-5f);
    m1 = s1 * (1.f / 128.f); v1 = q1s * (1.f / 128.f) - m1 * m1; rs1 = rsqrtf(v1 + 1e-5f);

#pragma unroll
    for (int nt = 0; nt < NT2; nt++) {
        int c = nt * 8 + tg * 2;
        float ga0 = g2v[c], ga1 = g2v[c + 1], be0 = bt2v[c], be1 = bt2v[c + 1];
        if (ok0) {
            float t0 = (acc2[nt].x - m0) * rs0 * ga0 + be0;
            float t1 = (acc2[nt].y - m0) * rs0 * ga1 + be1;
            float2 e = *(float2*)&xbuf[(size_t)r0 * DD + c];
            e.x += t0; e.y += t1;
            *(float2*)&xbuf[(size_t)r0 * DD + c] = e;
        }
        if (ok1) {
            float t0 = (acc2[nt].z - m1) * rs1 * ga0 + be0;
            float t1 = (acc2[nt].w - m1) * rs1 * ga1 + be1;
            float2 e = *(float2*)&xbuf[(size_t)r1 * DD + c];
            e.x += t0; e.y += t1;
            *(float2*)&xbuf[(size_t)r1 * DD + c] = e;
        }
    }
}

// ---------------- host launcher ----------------
extern "C" void kernel_launch(void* const* d_in, const int* in_sizes, int n_in,
                              void* d_out, int out_size) {
    const float* x    = (const float*)d_in[0];
    const int*   ei   = (const int*)d_in[1];
    const float* ea   = (const float*)d_in[2];
    const float* ew1  = (const float*)d_in[3];
    const float* eb1  = (const float*)d_in[4];
    const float* eg1  = (const float*)d_in[5];
    const float* ebt1 = (const float*)d_in[6];
    const float* ew2  = (const float*)d_in[7];
    const float* eb2  = (const float*)d_in[8];
    const float* eg2  = (const float*)d_in[9];
    const float* ebt2 = (const float*)d_in[10];
    const float* nw1  = (const float*)d_in[11];
    const float* nb1  = (const float*)d_in[12];
    const float* ng1  = (const float*)d_in[13];
    const float* nbt1 = (const float*)d_in[14];
    const float* nw2  = (const float*)d_in[15];
    const float* nb2  = (const float*)d_in[16];
    const float* ng2  = (const float*)d_in[17];
    const float* nbt2 = (const float*)d_in[18];

    float* xo = (float*)d_out;
    float* eo = xo + (size_t)NN * DD;
    const int* rowi = ei;
    const int* coli = ei + NE;

    uint4 *ew1a, *ew1b, *ew1c, *ew2p, *nw1p, *nw2p;
    cudaGetSymbolAddress((void**)&ew1a, g_ew1a);
    cudaGetSymbolAddress((void**)&ew1b, g_ew1b);
    cudaGetSymbolAddress((void**)&ew1c, g_ew1c);
    cudaGetSymbolAddress((void**)&ew2p, g_ew2p);
    cudaGetSymbolAddress((void**)&nw1p, g_nw1p);
    cudaGetSymbolAddress((void**)&nw2p, g_nw2p);

    const int SMEM = 4 * 32 * 32 * 16;  // 65536 (max slab ring)
    cudaFuncSetAttribute(pre_x1, cudaFuncAttributeMaxDynamicSharedMemorySize, SMEM);
    cudaFuncSetAttribute(edge_fused, cudaFuncAttributeMaxDynamicSharedMemorySize, SMEM);
    cudaFuncSetAttribute(node_fused, cudaFuncAttributeMaxDynamicSharedMemorySize, SMEM);

    // pack weights into B-fragment layout
    {
        int ta = NLAYERS * 8 * 32 * 32;
        int t2 = NLAYERS * 16 * 16 * 32;
        int t3 = NLAYERS * 16 * 32 * 32;
        pack_w<<<(ta + 255) / 256, 256>>>(ew1, ew1a, 0, 8, 32, 384, 256, ta);
        pack_w<<<(ta + 255) / 256, 256>>>(ew1, ew1b, 128, 8, 32, 384, 256, ta);
        pack_w<<<(ta + 255) / 256, 256>>>(ew1, ew1c, 256, 8, 32, 384, 256, ta);
        pack_w<<<(t2 + 255) / 256, 256>>>(ew2, ew2p, 0, 16, 16, 256, 128, t2);
        pack_w<<<(t3 + 255) / 256, 256>>>(nw1, nw1p, 0, 16, 32, 256, 256, t3);
        pack_w<<<(t2 + 255) / 256, 256>>>(nw2, nw2p, 0, 16, 16, 256, 128, t2);
    }

    copy_kernel<<<(NN * DD + 255) / 256, 256>>>(x, xo, NN * DD);
    copy_kernel<<<(NE * DD + 255) / 256, 256>>>(ea, eo, NE * DD);
    zero_cnt_kernel<<<(NN + 255) / 256, 256>>>();
    count_kernel<<<(NE + 255) / 256, 256>>>(coli);
    invcnt_kernel<<<(NN + 255) / 256, 256>>>();
    zero_agg_kernel<<<(NN * DD + 255) / 256, 256>>>();  // once; node phase-1 re-zeroes per layer

    const int EG = (ERT + 3) / 4;  // 938
    const int NG = (NRT + 3) / 4;  // 157

    for (int l = 0; l < NLAYERS; l++) {
        pre_x1<<<dim3(NG, 2), 128, SMEM>>>(
            ew1a + (size_t)l * 8 * 32 * 32, ew1b + (size_t)l * 8 * 32 * 32,
            eb1 + l * 256, xo);
        edge_fused<<<EG, 128, SMEM>>>(
            ew1c + (size_t)l * 8 * 32 * 32, ew2p + (size_t)l * 16 * 16 * 32,
            eg1 + l * 256, ebt1 + l * 256,
            eb2 + l * 128, eg2 + l * 128, ebt2 + l * 128,
            eo, rowi, coli);
        node_fused<<<NG, 128, SMEM>>>(
            nw1p + (size_t)l * 16 * 32 * 32, nw2p + (size_t)l * 16 * 16 * 32,
            nb1 + l * 256, ng1 + l * 256, nbt1 + l * 256,
            nb2 + l * 128, ng2 + l * 128, nbt2 + l * 128,
            xo);
    }
}

// round 16
// speedup vs baseline: 1.0773x; 1.0561x over previous
#include <cuda_runtime.h>
#include <cuda_fp16.h>
#include <math.h>
#include <stdint.h>

#define NN 10000
#define NE 60000
#define DD 128
#define NLAYERS 15

#define ERT 3750   // edge row tiles (60000/16)
#define NRT 625    // node row tiles (10000/16)

// ---------------- device scratch (allocation-free) ----------------
__device__ float g_agg[NN * DD];    // per-node aggregated edge features
__device__ float g_cnt[NN];         // 1/max(count,1)
__device__ float g_X1[NN * 512];    // per-node [x@W1a + b1 | x@W1b] (fp32)

// weights pre-packed as B-fragments {bh0,bh1,bl0,bl1} (fp16 hi/lo):
// layout [layer][ktile][ntile][lane]
__device__ uint4 g_ew1a[NLAYERS * 8 * 32 * 32];   // W1 rows 0..127   (x[row] part)
__device__ uint4 g_ew1b[NLAYERS * 8 * 32 * 32];   // W1 rows 128..255 (x[col] part)
__device__ uint4 g_ew1c[NLAYERS * 8 * 32 * 32];   // W1 rows 256..383 (ea part)
__device__ uint4 g_ew2p[NLAYERS * 16 * 16 * 32];
__device__ uint4 g_nw1p[NLAYERS * 16 * 32 * 32];
__device__ uint4 g_nw2p[NLAYERS * 16 * 16 * 32];

// ---------------- helpers ----------------
__device__ __forceinline__ uint32_t pkh(float a, float b) {
    __half2 t = __floats2half2_rn(a, b);
    return *(uint32_t*)&t;
}
__device__ __forceinline__ uint32_t pkl(float a, float b) {
    __half ha = __float2half_rn(a), hb = __float2half_rn(b);
    return pkh(a - __half2float(ha), b - __half2float(hb));
}

// exact-GELU via Abramowitz-Stegun 7.1.26 erf (abs err <= 1.5e-7)
__device__ __forceinline__ float gelu_f(float t) {
    float x = fabsf(t) * 0.70710678118654752f;
    float k = __fdividef(1.f, fmaf(0.3275911f, x, 1.f));
    float p = fmaf(1.061405429f, k, -1.453152027f);
    p = fmaf(p, k, 1.421413741f);
    p = fmaf(p, k, -0.284496736f);
    p = fmaf(p, k, 0.254829592f);
    p = p * k;
    float e = __expf(-x * x);
    float er = copysignf(fmaf(-p, e, 1.f), t);
    return 0.5f * t * (1.f + er);
}

#define MMA4(d, a, b0, b1) \
    asm volatile("mma.sync.aligned.m16n8k16.row.col.f32.f16.f16.f32 " \
                 "{%0,%1,%2,%3},{%4,%5,%6,%7},{%8,%9},{%0,%1,%2,%3};" \
                 : "+f"((d).x), "+f"((d).y), "+f"((d).z), "+f"((d).w) \
                 : "r"((a)[0]), "r"((a)[1]), "r"((a)[2]), "r"((a)[3]), \
                   "r"(b0), "r"(b1))

#define REDV2(ptr, v0, v1) \
    asm volatile("red.global.add.v2.f32 [%0], {%1, %2};" \
                 :: "l"(ptr), "f"(v0), "f"(v1) : "memory")

// async B slab prefetch into 4-deep ring slot (kt & 3); always commits a group
template <int SLAB, int NTH>
__device__ __forceinline__ void pref_slab(uint4* sB, const uint4* Wp, int kt, int KT, int tid) {
    if (kt < KT) {
        const uint4* src = Wp + (size_t)kt * SLAB + tid;
        uint32_t dst = (uint32_t)__cvta_generic_to_shared(sB + (kt & 3) * SLAB + tid);
#pragma unroll
        for (int i = 0; i < SLAB / NTH; i++)
            asm volatile("cp.async.cg.shared.global [%0], [%1], 16;"
                         :: "r"(dst + i * NTH * 16), "l"(src + i * NTH));
    }
    asm volatile("cp.async.commit_group;" ::: "memory");
}
#define CPWAIT2() asm volatile("cp.async.wait_group 2;" ::: "memory")
#define CPWAIT0() asm volatile("cp.async.wait_group 0;" ::: "memory")

// ---------------- aux kernels ----------------
__global__ void copy_kernel(const float* __restrict__ src, float* __restrict__ dst, int n) {
    int i = blockIdx.x * blockDim.x + threadIdx.x;
    if (i < n) dst[i] = src[i];
}
__global__ void zero_cnt_kernel() {
    int i = blockIdx.x * blockDim.x + threadIdx.x;
    if (i < NN) g_cnt[i] = 0.f;
}
__global__ void count_kernel(const int* __restrict__ col) {
    int e = blockIdx.x * blockDim.x + threadIdx.x;
    if (e < NE) atomicAdd(&g_cnt[col[e]], 1.f);
}
__global__ void invcnt_kernel() {
    int i = blockIdx.x * blockDim.x + threadIdx.x;
    if (i < NN) g_cnt[i] = 1.f / fmaxf(g_cnt[i], 1.f);
}
__global__ void zero_agg_kernel() {
    int i = blockIdx.x * blockDim.x + threadIdx.x;
    if (i < NN * DD) g_agg[i] = 0.f;
}

// Pre-pack fp32 W[L][K][N] rows [k0, k0+16*KT) into per-lane B fragments.
__global__ void pack_w(const float* __restrict__ W, uint4* __restrict__ out,
                       int k0, int KT, int NT, int K, int N, int total) {
    int idx = blockIdx.x * blockDim.x + threadIdx.x;
    if (idx >= total) return;
    int lane = idx & 31;
    int t = idx >> 5;
    int nt = t % NT; t /= NT;
    int kt = t % KT;
    int l = t / KT;
    int g = lane >> 2, tg = lane & 3;
    const float* Wl = W + (size_t)l * K * N;
    int n = nt * 8 + g;
    int ka = k0 + kt * 16 + tg * 2;
    float v00 = Wl[(size_t)ka * N + n];
    float v01 = Wl[(size_t)(ka + 1) * N + n];
    float v10 = Wl[(size_t)(ka + 8) * N + n];
    float v11 = Wl[(size_t)(ka + 9) * N + n];
    uint4 o;
    o.x = pkh(v00, v01);
    o.y = pkh(v10, v11);
    o.z = pkl(v00, v01);
    o.w = pkl(v10, v11);
    out[idx] = o;
}

// ---------------- per-layer node precompute: X1 = [x@W1a + b1 | x@W1b] ----------------
// blockIdx.y = 0: W1a half (adds bias), 1: W1b half. K=128 (8 ktiles), N=256.
// 3 CTAs/SM: grid 314 fits one wave (444 slots) instead of a ragged 2nd wave.
__global__ void __launch_bounds__(128, 3)
pre_x1(const uint4* __restrict__ Wa, const uint4* __restrict__ Wb,
       const float* __restrict__ b1v, const float* __restrict__ xbuf) {
    constexpr int KT = 8, NT = 32, SLAB = NT * 32;
    extern __shared__ uint4 sB[];

    const int tid = threadIdx.x, lane = tid & 31, warp = tid >> 5;
    const int g = lane >> 2, tg = lane & 3;
    const int half = blockIdx.y;
    const uint4* Wp = half ? Wb : Wa;
    const int rt = blockIdx.x * 4 + warp;
    const int r0 = rt * 16 + g, r1 = r0 + 8;
    const int r0c = min(r0, NN - 1), r1c = min(r1, NN - 1);
    const bool ok0 = r0 < NN, ok1 = r1 < NN;

    const float* p0 = xbuf + (size_t)r0c * DD;
    const float* p1 = xbuf + (size_t)r1c * DD;

    float4 acc[NT];
#pragma unroll
    for (int i = 0; i < NT; i++) acc[i] = make_float4(0.f, 0.f, 0.f, 0.f);

    pref_slab<SLAB, 128>(sB, Wp, 0, KT, tid);
    pref_slab<SLAB, 128>(sB, Wp, 1, KT, tid);
    pref_slab<SLAB, 128>(sB, Wp, 2, KT, tid);

    for (int kt = 0; kt < KT; kt++) {
        CPWAIT2();
        __syncthreads();
        int ko = kt * 16 + tg * 2;
        float2 a0 = *(const float2*)(p0 + ko);
        float2 a2 = *(const float2*)(p0 + ko + 8);
        float2 b0 = *(const float2*)(p1 + ko);
        float2 b2 = *(const float2*)(p1 + ko + 8);
        uint32_t ah[4];
        ah[0] = pkh(a0.x, a0.y); ah[1] = pkh(b0.x, b0.y);
        ah[2] = pkh(a2.x, a2.y); ah[3] = pkh(b2.x, b2.y);
        const uint4* Bs = sB + (kt & 3) * SLAB + lane;
#pragma unroll
        for (int nt = 0; nt < NT; nt++) {
            uint4 b = Bs[nt * 32];
            MMA4(acc[nt], ah, b.x, b.y);
            MMA4(acc[nt], ah, b.z, b.w);
        }
        pref_slab<SLAB, 128>(sB, Wp, kt + 3, KT, tid);
    }

    const int ofs = half * 256;
#pragma unroll
    for (int nt = 0; nt < NT; nt++) {
        int c = nt * 8 + tg * 2;
        float bx = half ? 0.f : b1v[c];
        float by = half ? 0.f : b1v[c + 1];
        if (ok0) *(float2*)&g_X1[(size_t)r0 * 512 + ofs + c] =
            make_float2(acc[nt].x + bx, acc[nt].y + by);
        if (ok1) *(float2*)&g_X1[(size_t)r1 * 512 + ofs + c] =
            make_float2(acc[nt].z + bx, acc[nt].w + by);
    }
}

// ---------------- fused edge MLP kernel ----------------
// GEMM1 = ea@W1c (K=128) + gathered X1[row], X1[col] adds (bias pre-folded);
// LN1 + GELU -> register fp16 fragments; GEMM2 K=256 N=128; LN2 + residual(ea)
// + red.v2 scatter into g_agg[col]. 4 warps/CTA, min 3 CTAs/SM
// (grid 938: 3.17 waves at 2/SM -> 2.11 waves at 3/SM).
__global__ void __launch_bounds__(128, 3)
edge_fused(const uint4* __restrict__ W1, const uint4* __restrict__ W2,
           const float* __restrict__ g1v, const float* __restrict__ bt1v,
           const float* __restrict__ b2v, const float* __restrict__ g2v, const float* __restrict__ bt2v,
           float* __restrict__ eabuf,
           const int* __restrict__ rowi, const int* __restrict__ coli) {
    constexpr int KT1 = 8, NT1 = 32, SLAB1 = NT1 * 32;
    constexpr int KT2 = 16, NT2 = 16, SLAB2 = NT2 * 32;
    extern __shared__ uint4 sB[];

    const int tid = threadIdx.x, lane = tid & 31, warp = tid >> 5;
    const int g = lane >> 2, tg = lane & 3;
    const int rt = blockIdx.x * 4 + warp;
    const int r0 = rt * 16 + g, r1 = r0 + 8;
    const int r0c = min(r0, NE - 1), r1c = min(r1, NE - 1);
    const bool ok0 = r0 < NE, ok1 = r1 < NE;

    const int n0r = rowi[r0c], n0c = coli[r0c];
    const int n1r = rowi[r1c], n1c = coli[r1c];
    const float* p02 = eabuf + (size_t)r0c * DD;
    const float* p12 = eabuf + (size_t)r1c * DD;

    // ---- phase 1: GEMM1 (ea @ W1c) ----
    float4 acc[NT1];
#pragma unroll
    for (int i = 0; i < NT1; i++) acc[i] = make_float4(0.f, 0.f, 0.f, 0.f);

    pref_slab<SLAB1, 128>(sB, W1, 0, KT1, tid);
    pref_slab<SLAB1, 128>(sB, W1, 1, KT1, tid);
    pref_slab<SLAB1, 128>(sB, W1, 2, KT1, tid);

    for (int kt = 0; kt < KT1; kt++) {
        CPWAIT2();
        __syncthreads();
        int ko = kt * 16 + tg * 2;
        float2 a0 = *(const float2*)(p02 + ko);
        float2 a2 = *(const float2*)(p02 + ko + 8);
        float2 b0 = *(const float2*)(p12 + ko);
        float2 b2 = *(const float2*)(p12 + ko + 8);
        uint32_t ah[4];
        ah[0] = pkh(a0.x, a0.y); ah[1] = pkh(b0.x, b0.y);
        ah[2] = pkh(a2.x, a2.y); ah[3] = pkh(b2.x, b2.y);
        const uint4* Bs = sB + (kt & 3) * SLAB1 + lane;
#pragma unroll
        for (int nt = 0; nt < NT1; nt++) {
            uint4 b = Bs[nt * 32];
            MMA4(acc[nt], ah, b.x, b.y);
            MMA4(acc[nt], ah, b.z, b.w);
        }
        pref_slab<SLAB1, 128>(sB, W1, kt + 3, KT1, tid);
    }

    // ---- gather-add X1 rows + LN1 stats ----
    const float* xa0 = g_X1 + (size_t)n0r * 512;
    const float* xb0 = g_X1 + (size_t)n0c * 512 + 256;
    const float* xa1 = g_X1 + (size_t)n1r * 512;
    const float* xb1 = g_X1 + (size_t)n1c * 512 + 256;
    float s0 = 0.f, q0s = 0.f, s1 = 0.f, q1s = 0.f;
#pragma unroll
    for (int nt = 0; nt < NT1; nt++) {
        int c = nt * 8 + tg * 2;
        float2 va = *(const float2*)(xa0 + c);
        float2 vb = *(const float2*)(xb0 + c);
        float2 vc = *(const float2*)(xa1 + c);
        float2 vd = *(const float2*)(xb1 + c);
        acc[nt].x += va.x + vb.x; acc[nt].y += va.y + vb.y;
        acc[nt].z += vc.x + vd.x; acc[nt].w += vc.y + vd.y;
        s0 += acc[nt].x + acc[nt].y;
        q0s += acc[nt].x * acc[nt].x + acc[nt].y * acc[nt].y;
        s1 += acc[nt].z + acc[nt].w;
        q1s += acc[nt].z * acc[nt].z + acc[nt].w * acc[nt].w;
    }
#pragma unroll
    for (int off = 1; off <= 2; off <<= 1) {
        s0 += __shfl_xor_sync(0xffffffffu, s0, off);
        q0s += __shfl_xor_sync(0xffffffffu, q0s, off);
        s1 += __shfl_xor_sync(0xffffffffu, s1, off);
        q1s += __shfl_xor_sync(0xffffffffu, q1s, off);
    }
    float m0 = s0 * (1.f / 256.f), v0 = q0s * (1.f / 256.f) - m0 * m0, rs0 = rsqrtf(v0 + 1e-5f);
    float m1 = s1 * (1.f / 256.f), v1 = q1s * (1.f / 256.f) - m1 * m1, rs1 = rsqrtf(v1 + 1e-5f);

    // ---- phase boundary: drain ring, start phase-2 prefetch, then GELU epilogue ----
    CPWAIT0();
    __syncthreads();
    pref_slab<SLAB2, 128>(sB, W2, 0, KT2, tid);
    pref_slab<SLAB2, 128>(sB, W2, 1, KT2, tid);
    pref_slab<SLAB2, 128>(sB, W2, 2, KT2, tid);

    uint4 hf[16];  // hidden rows as fp16 A-fragments for GEMM2
#pragma unroll
    for (int kt = 0; kt < 16; kt++) {
        int c = kt * 16 + tg * 2;
        float ga0 = g1v[c], ga1 = g1v[c + 1], be0 = bt1v[c], be1 = bt1v[c + 1];
        float ga2 = g1v[c + 8], ga3 = g1v[c + 9], be2 = bt1v[c + 8], be3 = bt1v[c + 9];
        float tv[8];
        tv[0] = (acc[2 * kt].x - m0) * rs0 * ga0 + be0;
        tv[1] = (acc[2 * kt].y - m0) * rs0 * ga1 + be1;
        tv[2] = (acc[2 * kt].z - m1) * rs1 * ga0 + be0;
        tv[3] = (acc[2 * kt].w - m1) * rs1 * ga1 + be1;
        tv[4] = (acc[2 * kt + 1].x - m0) * rs0 * ga2 + be2;
        tv[5] = (acc[2 * kt + 1].y - m0) * rs0 * ga3 + be3;
        tv[6] = (acc[2 * kt + 1].z - m1) * rs1 * ga2 + be2;
        tv[7] = (acc[2 * kt + 1].w - m1) * rs1 * ga3 + be3;
#pragma unroll
        for (int j = 0; j < 8; j++) tv[j] = gelu_f(tv[j]);
        hf[kt].x = pkh(tv[0], tv[1]); hf[kt].y = pkh(tv[2], tv[3]);
        hf[kt].z = pkh(tv[4], tv[5]); hf[kt].w = pkh(tv[6], tv[7]);
    }

    // ---- phase 2: GEMM2 (A from registers) ----
    float4 acc2[NT2];
#pragma unroll
    for (int i = 0; i < NT2; i++) acc2[i] = make_float4(0.f, 0.f, 0.f, 0.f);

    for (int kt = 0; kt < KT2; kt++) {
        CPWAIT2();
        __syncthreads();
        uint32_t ah[4] = {hf[kt].x, hf[kt].y, hf[kt].z, hf[kt].w};
        const uint4* Bs = sB + (kt & 3) * SLAB2 + lane;
#pragma unroll
        for (int nt = 0; nt < NT2; nt++) {
            uint4 b = Bs[nt * 32];
            MMA4(acc2[nt], ah, b.x, b.y);
            MMA4(acc2[nt], ah, b.z, b.w);
        }
        pref_slab<SLAB2, 128>(sB, W2, kt + 3, KT2, tid);
    }

    // ---- LN2 + residual(ea) + agg scatter (red.v2) ----
    s0 = 0.f; q0s = 0.f; s1 = 0.f; q1s = 0.f;
#pragma unroll
    for (int nt = 0; nt < NT2; nt++) {
        int c = nt * 8 + tg * 2;
        float bx = b2v[c], by = b2v[c + 1];
        acc2[nt].x += bx; acc2[nt].y += by;
        acc2[nt].z += bx; acc2[nt].w += by;
        s0 += acc2[nt].x + acc2[nt].y;
        q0s += acc2[nt].x * acc2[nt].x + acc2[nt].y * acc2[nt].y;
        s1 += acc2[nt].z + acc2[nt].w;
        q1s += acc2[nt].z * acc2[nt].z + acc2[nt].w * acc2[nt].w;
    }
#pragma unroll
    for (int off = 1; off <= 2; off <<= 1) {
        s0 += __shfl_xor_sync(0xffffffffu, s0, off);
        q0s += __shfl_xor_sync(0xffffffffu, q0s, off);
        s1 += __shfl_xor_sync(0xffffffffu, s1, off);
        q1s += __shfl_xor_sync(0xffffffffu, q1s, off);
    }
    m0 = s0 * (1.f / 128.f); v0 = q0s * (1.f / 128.f) - m0 * m0; rs0 = rsqrtf(v0 + 1e-5f);
    m1 = s1 * (1.f / 128.f); v1 = q1s * (1.f / 128.f) - m1 * m1; rs1 = rsqrtf(v1 + 1e-5f);

#pragma unroll
    for (int nt = 0; nt < NT2; nt++) {
        int c = nt * 8 + tg * 2;
        float ga0 = g2v[c], ga1 = g2v[c + 1], be0 = bt2v[c], be1 = bt2v[c + 1];
        if (ok0) {
            float t0 = (acc2[nt].x - m0) * rs0 * ga0 + be0;
            float t1 = (acc2[nt].y - m0) * rs0 * ga1 + be1;
            float2 e = *(float2*)&eabuf[(size_t)r0 * DD + c];
            e.x += t0; e.y += t1;
            *(float2*)&eabuf[(size_t)r0 * DD + c] = e;
            REDV2(&g_agg[(size_t)n0c * DD + c], e.x, e.y);
        }
        if (ok1) {
            float t0 = (acc2[nt].z - m1) * rs1 * ga0 + be0;
            float t1 = (acc2[nt].w - m1) * rs1 * ga1 + be1;
            float2 e = *(float2*)&eabuf[(size_t)r1 * DD + c];
            e.x += t0; e.y += t1;
            *(float2*)&eabuf[(size_t)r1 * DD + c] = e;
            REDV2(&g_agg[(size_t)n1c * DD + c], e.x, e.y);
        }
    }
}

// ---------------- fused node MLP kernel ----------------
// A1=[x | agg*invcnt] K=256 N=256 (re-zeroes agg for next layer);
// GEMM2 K=256 N=128; out: x += LN2. 4 warps/CTA, min 2 CTAs/SM
// (grid 157 = single wave already; keeps register headroom).
__global__ void __launch_bounds__(128, 2)
node_fused(const uint4* __restrict__ W1, const uint4* __restrict__ W2,
           const float* __restrict__ b1v, const float* __restrict__ g1v, const float* __restrict__ bt1v,
           const float* __restrict__ b2v, const float* __restrict__ g2v, const float* __restrict__ bt2v,
           float* __restrict__ xbuf) {
    constexpr int KT1 = 16, NT1 = 32, SLAB1 = NT1 * 32;
    constexpr int KT2 = 16, NT2 = 16, SLAB2 = NT2 * 32;
    extern __shared__ uint4 sB[];

    const int tid = threadIdx.x, lane = tid & 31, warp = tid >> 5;
    const int g = lane >> 2, tg = lane & 3;
    const int rt = blockIdx.x * 4 + warp;
    const int r0 = rt * 16 + g, r1 = r0 + 8;
    const int r0c = min(r0, NN - 1), r1c = min(r1, NN - 1);
    const bool ok0 = r0 < NN, ok1 = r1 < NN;

    const float* p00 = xbuf + (size_t)r0c * DD;
    float* p01 = g_agg + (size_t)r0c * DD;
    const float* p10 = xbuf + (size_t)r1c * DD;
    float* p11 = g_agg + (size_t)r1c * DD;
    const float ic0 = g_cnt[r0c], ic1 = g_cnt[r1c];

    auto loadA = [&](int kt, float2& a0, float2& a2, float2& b0, float2& b2) {
        int seg = kt >> 3, ko = (kt & 7) * 16 + tg * 2;
        const float* q0 = seg == 0 ? p00 : p01;
        const float* q1 = seg == 0 ? p10 : p11;
        a0 = *(const float2*)(q0 + ko); a2 = *(const float2*)(q0 + ko + 8);
        b0 = *(const float2*)(q1 + ko); b2 = *(const float2*)(q1 + ko + 8);
        if (seg == 1) {
            // each agg element read exactly once per layer: zero it for the next
            // layer's scatter. Guarded so clamped (out-of-range) warps never write.
            float2 z = make_float2(0.f, 0.f);
            if (ok0) { *(float2*)(p01 + ko) = z; *(float2*)(p01 + ko + 8) = z; }
            if (ok1) { *(float2*)(p11 + ko) = z; *(float2*)(p11 + ko + 8) = z; }
        }
    };

    // ---- phase 1: GEMM1 ----
    float4 acc[NT1];
#pragma unroll
    for (int i = 0; i < NT1; i++) acc[i] = make_float4(0.f, 0.f, 0.f, 0.f);

    pref_slab<SLAB1, 128>(sB, W1, 0, KT1, tid);
    pref_slab<SLAB1, 128>(sB, W1, 1, KT1, tid);
    pref_slab<SLAB1, 128>(sB, W1, 2, KT1, tid);
    float2 ca0, ca2, cb0, cb2;
    loadA(0, ca0, ca2, cb0, cb2);

    for (int kt = 0; kt < KT1; kt++) {
        CPWAIT2();
        __syncthreads();
        float2 na0 = ca0, na2 = ca2, nb0 = cb0, nb2 = cb2;
        if (kt + 1 < KT1) loadA(kt + 1, na0, na2, nb0, nb2);
        float s0f = 1.f, s1f = 1.f;
        if ((kt >> 3) == 1) { s0f = ic0; s1f = ic1; }
        uint32_t ah[4];
        ah[0] = pkh(ca0.x * s0f, ca0.y * s0f);
        ah[1] = pkh(cb0.x * s1f, cb0.y * s1f);
        ah[2] = pkh(ca2.x * s0f, ca2.y * s0f);
        ah[3] = pkh(cb2.x * s1f, cb2.y * s1f);
        const uint4* Bs = sB + (kt & 3) * SLAB1 + lane;
#pragma unroll
        for (int nt = 0; nt < NT1; nt++) {
            uint4 b = Bs[nt * 32];
            MMA4(acc[nt], ah, b.x, b.y);
            MMA4(acc[nt], ah, b.z, b.w);
        }
        pref_slab<SLAB1, 128>(sB, W1, kt + 3, KT1, tid);
        ca0 = na0; ca2 = na2; cb0 = nb0; cb2 = nb2;
    }

    // ---- LN1 stats ----
    float s0 = 0.f, q0s = 0.f, s1 = 0.f, q1s = 0.f;
#pragma unroll
    for (int nt = 0; nt < NT1; nt++) {
        int c = nt * 8 + tg * 2;
        float bx = b1v[c], by = b1v[c + 1];
        acc[nt].x += bx; acc[nt].y += by;
        acc[nt].z += bx; acc[nt].w += by;
        s0 += acc[nt].x + acc[nt].y;
        q0s += acc[nt].x * acc[nt].x + acc[nt].y * acc[nt].y;
        s1 += acc[nt].z + acc[nt].w;
        q1s += acc[nt].z * acc[nt].z + acc[nt].w * acc[nt].w;
    }
#pragma unroll
    for (int off = 1; off <= 2; off <<= 1) {
        s0 += __shfl_xor_sync(0xffffffffu, s0, off);
        q0s += __shfl_xor_sync(0xffffffffu, q0s, off);
        s1 += __shfl_xor_sync(0xffffffffu, s1, off);
        q1s += __shfl_xor_sync(0xffffffffu, q1s, off);
    }
    float m0 = s0 * (1.f / 256.f), v0 = q0s * (1.f / 256.f) - m0 * m0, rs0 = rsqrtf(v0 + 1e-5f);
    float m1 = s1 * (1.f / 256.f), v1 = q1s * (1.f / 256.f) - m1 * m1, rs1 = rsqrtf(v1 + 1e-5f);

    // ---- phase boundary ----
    CPWAIT0();
    __syncthreads();
    pref_slab<SLAB2, 128>(sB, W2, 0, KT2, tid);
    pref_slab<SLAB2, 128>(sB, W2, 1, KT2, tid);
    pref_slab<SLAB2, 128>(sB, W2, 2, KT2, tid);

    uint4 hf[16];
#pragma unroll
    for (int kt = 0; kt < 16; kt++) {
        int c = kt * 16 + tg * 2;
        float ga0 = g1v[c], ga1 = g1v[c + 1], be0 = bt1v[c], be1 = bt1v[c + 1];
        float ga2 = g1v[c + 8], ga3 = g1v[c + 9], be2 = bt1v[c + 8], be3 = bt1v[c + 9];
        float tv[8];
        tv[0] = (acc[2 * kt].x - m0) * rs0 * ga0 + be0;
        tv[1] = (acc[2 * kt].y - m0) * rs0 * ga1 + be1;
        tv[2] = (acc[2 * kt].z - m1) * rs1 * ga0 + be0;
        tv[3] = (acc[2 * kt].w - m1) * rs1 * ga1 + be1;
        tv[4] = (acc[2 * kt + 1].x - m0) * rs0 * ga2 + be2;
        tv[5] = (acc[2 * kt + 1].y - m0) * rs0 * ga3 + be3;
        tv[6] = (acc[2 * kt + 1].z - m1) * rs1 * ga2 + be2;
        tv[7] = (acc[2 * kt + 1].w - m1) * rs1 * ga3 + be3;
#pragma unroll
        for (int j = 0; j < 8; j++) tv[j] = gelu_f(tv[j]);
        hf[kt].x = pkh(tv[0], tv[1]); hf[kt].y = pkh(tv[2], tv[3]);
        hf[kt].z = pkh(tv[4], tv[5]); hf[kt].w = pkh(tv[6], tv[7]);
    }

    // ---- phase 2: GEMM2 ----
    float4 acc2[NT2];
#pragma unroll
    for (int i = 0; i < NT2; i++) acc2[i] = make_float4(0.f, 0.f, 0.f, 0.f);

    for (int kt = 0; kt < KT2; kt++) {
        CPWAIT2();
        __syncthreads();
        uint32_t ah[4] = {hf[kt].x, hf[kt].y, hf[kt].z, hf[kt].w};
        const uint4* Bs = sB + (kt & 3) * SLAB2 + lane;
#pragma unroll
        for (int nt = 0; nt < NT2; nt++) {
            uint4 b = Bs[nt * 32];
            MMA4(acc2[nt], ah, b.x, b.y);
            MMA4(acc2[nt], ah, b.z, b.w);
        }
        pref_slab<SLAB2, 128>(sB, W2, kt + 3, KT2, tid);
    }

    // ---- LN2 + residual(x) ----
    s0 = 0.f; q0s = 0.f; s1 = 0.f; q1s = 0.f;
#pragma unroll
    for (int nt = 0; nt < NT2; nt++) {
        int c = nt * 8 + tg * 2;
        float bx = b2v[c], by = b2v[c + 1];
        acc2[nt].x += bx; acc2[nt].y += by;
        acc2[nt].z += bx; acc2[nt].w += by;
        s0 += acc2[nt].x + acc2[nt].y;
        q0s += acc2[nt].x * acc2[nt].x + acc2[nt].y * acc2[nt].y;
        s1 += acc2[nt].z + acc2[nt].w;
        q1s += acc2[nt].z * acc2[nt].z + acc2[nt].w * acc2[nt].w;
    }
#pragma unroll
    for (int off = 1; off <= 2; off <<= 1) {
        s0 += __shfl_xor_sync(0xffffffffu, s0, off);
        q0s += __shfl_xor_sync(0xffffffffu, q0s, off);
        s1 += __shfl_xor_sync(0xffffffffu, s1, off);
        q1s += __shfl_xor_sync(0xffffffffu, q1s, off);
    }
    m0 = s0 * (1.f / 128.f); v0 = q0s * (1.f / 128.f) - m0 * m0; rs0 = rsqrtf(v0 + 1e-5f);
    m1 = s1 * (1.f / 128.f); v1 = q1s * (1.f / 128.f) - m1 * m1; rs1 = rsqrtf(v1 + 1e-5f);

#pragma unroll
    for (int nt = 0; nt < NT2; nt++) {
        int c = nt * 8 + tg * 2;
        float ga0 = g2v[c], ga1 = g2v[c + 1], be0 = bt2v[c], be1 = bt2v[c + 1];
        if (ok0) {
            float t0 = (acc2[nt].x - m0) * rs0 * ga0 + be0;
            float t1 = (acc2[nt].y - m0) * rs0 * ga1 + be1;
            float2 e = *(float2*)&xbuf[(size_t)r0 * DD + c];
            e.x += t0; e.y += t1;
            *(float2*)&xbuf[(size_t)r0 * DD + c] = e;
        }
        if (ok1) {
            float t0 = (acc2[nt].z - m1) * rs1 * ga0 + be0;
            float t1 = (acc2[nt].w - m1) * rs1 * ga1 + be1;
            float2 e = *(float2*)&xbuf[(size_t)r1 * DD + c];
            e.x += t0; e.y += t1;
            *(float2*)&xbuf[(size_t)r1 * DD + c] = e;
        }
    }
}

// ---------------- host launcher ----------------
extern "C" void kernel_launch(void* const* d_in, const int* in_sizes, int n_in,
                              void* d_out, int out_size) {
    const float* x    = (const float*)d_in[0];
    const int*   ei   = (const int*)d_in[1];
    const float* ea   = (const float*)d_in[2];
    const float* ew1  = (const float*)d_in[3];
    const float* eb1  = (const float*)d_in[4];
    const float* eg1  = (const float*)d_in[5];
    const float* ebt1 = (const float*)d_in[6];
    const float* ew2  = (const float*)d_in[7];
    const float* eb2  = (const float*)d_in[8];
    const float* eg2  = (const float*)d_in[9];
    const float* ebt2 = (const float*)d_in[10];
    const float* nw1  = (const float*)d_in[11];
    const float* nb1  = (const float*)d_in[12];
    const float* ng1  = (const float*)d_in[13];
    const float* nbt1 = (const float*)d_in[14];
    const float* nw2  = (const float*)d_in[15];
    const float* nb2  = (const float*)d_in[16];
    const float* ng2  = (const float*)d_in[17];
    const float* nbt2 = (const float*)d_in[18];

    float* xo = (float*)d_out;
    float* eo = xo + (size_t)NN * DD;
    const int* rowi = ei;
    const int* coli = ei + NE;

    uint4 *ew1a, *ew1b, *ew1c, *ew2p, *nw1p, *nw2p;
    cudaGetSymbolAddress((void**)&ew1a, g_ew1a);
    cudaGetSymbolAddress((void**)&ew1b, g_ew1b);
    cudaGetSymbolAddress((void**)&ew1c, g_ew1c);
    cudaGetSymbolAddress((void**)&ew2p, g_ew2p);
    cudaGetSymbolAddress((void**)&nw1p, g_nw1p);
    cudaGetSymbolAddress((void**)&nw2p, g_nw2p);

    const int SMEM = 4 * 32 * 32 * 16;  // 65536 (max slab ring)
    cudaFuncSetAttribute(pre_x1, cudaFuncAttributeMaxDynamicSharedMemorySize, SMEM);
    cudaFuncSetAttribute(edge_fused, cudaFuncAttributeMaxDynamicSharedMemorySize, SMEM);
    cudaFuncSetAttribute(node_fused, cudaFuncAttributeMaxDynamicSharedMemorySize, SMEM);

    // pack weights into B-fragment layout
    {
        int ta = NLAYERS * 8 * 32 * 32;
        int t2 = NLAYERS * 16 * 16 * 32;
        int t3 = NLAYERS * 16 * 32 * 32;
        pack_w<<<(ta + 255) / 256, 256>>>(ew1, ew1a, 0, 8, 32, 384, 256, ta);
        pack_w<<<(ta + 255) / 256, 256>>>(ew1, ew1b, 128, 8, 32, 384, 256, ta);
        pack_w<<<(ta + 255) / 256, 256>>>(ew1, ew1c, 256, 8, 32, 384, 256, ta);
        pack_w<<<(t2 + 255) / 256, 256>>>(ew2, ew2p, 0, 16, 16, 256, 128, t2);
        pack_w<<<(t3 + 255) / 256, 256>>>(nw1, nw1p, 0, 16, 32, 256, 256, t3);
        pack_w<<<(t2 + 255) / 256, 256>>>(nw2, nw2p, 0, 16, 16, 256, 128, t2);
    }

    copy_kernel<<<(NN * DD + 255) / 256, 256>>>(x, xo, NN * DD);
    copy_kernel<<<(NE * DD + 255) / 256, 256>>>(ea, eo, NE * DD);
    zero_cnt_kernel<<<(NN + 255) / 256, 256>>>();
    count_kernel<<<(NE + 255) / 256, 256>>>(coli);
    invcnt_kernel<<<(NN + 255) / 256, 256>>>();
    zero_agg_kernel<<<(NN * DD + 255) / 256, 256>>>();  // once; node phase-1 re-zeroes per layer

    const int EG = (ERT + 3) / 4;  // 938
    const int NG = (NRT + 3) / 4;  // 157

    for (int l = 0; l < NLAYERS; l++) {
        pre_x1<<<dim3(NG, 2), 128, SMEM>>>(
            ew1a + (size_t)l * 8 * 32 * 32, ew1b + (size_t)l * 8 * 32 * 32,
            eb1 + l * 256, xo);
        edge_fused<<<EG, 128, SMEM>>>(
            ew1c + (size_t)l * 8 * 32 * 32, ew2p + (size_t)l * 16 * 16 * 32,
            eg1 + l * 256, ebt1 + l * 256,
            eb2 + l * 128, eg2 + l * 128, ebt2 + l * 128,
            eo, rowi, coli);
        node_fused<<<NG, 128, SMEM>>>(
            nw1p + (size_t)l * 16 * 32 * 32, nw2p + (size_t)l * 16 * 16 * 32,
            nb1 + l * 256, ng1 + l * 256, nbt1 + l * 256,
            nb2 + l * 128, ng2 + l * 128, nbt2 + l * 128,
            xo);
    }
}